// round 2
// baseline (speedup 1.0000x reference)
#include <cuda_runtime.h>
#include <math.h>

#define S_LEN 2048
#define D_DIM 1024
#define NHEAD 16
#define HD 64
#define MROWS 4096
#define PQ 68

// Scratch (device globals: no allocations allowed)
__device__ float g_q[MROWS * D_DIM];    // [b,h,s,d]
__device__ float g_k[MROWS * D_DIM];    // [b,h,s,d]
__device__ float g_v[MROWS * D_DIM];    // [b,h,s,d]
__device__ float g_ctx[MROWS * D_DIM];  // [b,s,h*64+d]
__device__ float g_x[MROWS * D_DIM];    // pre-LN

// ---------------------------------------------------------------------------
// SGEMM: C = A[4096x1024] @ W[1024x1024] + bias
// MODE 0/1/2: write q/k/v in head layout.  MODE 3: A=g_ctx, += resid, -> g_x
// ---------------------------------------------------------------------------
template <int MODE>
__global__ __launch_bounds__(256, 2) void gemm_k(
    const float* __restrict__ A,
    const float* __restrict__ W,
    const float* __restrict__ bias,
    const float* __restrict__ resid)
{
    constexpr int N = D_DIM, K = D_DIM;
    __shared__ float As[8][132];
    __shared__ float Bs[8][128];
    const int tid  = threadIdx.x;
    const int brow = blockIdx.y * 128;
    const int bcol = blockIdx.x * 128;
    const int arow = tid >> 1;
    const int acol = (tid & 1) << 2;
    const int brl  = tid >> 5;
    const int bcl  = (tid & 31) << 2;
    const int tx = tid & 15;
    const int ty = tid >> 4;

    const float* Ap = (MODE == 3) ? (const float*)g_ctx : A;

    float acc[8][8];
#pragma unroll
    for (int i = 0; i < 8; i++)
#pragma unroll
        for (int j = 0; j < 8; j++) acc[i][j] = 0.f;

    const float* aptr = Ap + (size_t)(brow + arow) * K + acol;
    const float* wptr = W + (size_t)brl * N + bcol + bcl;

    for (int k0 = 0; k0 < K; k0 += 8) {
        float4 av = *(const float4*)(aptr + k0);
        float4 wv = *(const float4*)(wptr + (size_t)k0 * N);
        As[acol + 0][arow] = av.x;
        As[acol + 1][arow] = av.y;
        As[acol + 2][arow] = av.z;
        As[acol + 3][arow] = av.w;
        *(float4*)&Bs[brl][bcl] = wv;
        __syncthreads();
#pragma unroll
        for (int kk = 0; kk < 8; kk++) {
            float4 a0 = *(const float4*)&As[kk][ty * 8];
            float4 a1 = *(const float4*)&As[kk][ty * 8 + 4];
            float4 b0 = *(const float4*)&Bs[kk][tx * 8];
            float4 b1 = *(const float4*)&Bs[kk][tx * 8 + 4];
            float ra[8] = {a0.x, a0.y, a0.z, a0.w, a1.x, a1.y, a1.z, a1.w};
            float rb[8] = {b0.x, b0.y, b0.z, b0.w, b1.x, b1.y, b1.z, b1.w};
#pragma unroll
            for (int i = 0; i < 8; i++)
#pragma unroll
                for (int j = 0; j < 8; j++)
                    acc[i][j] = fmaf(ra[i], rb[j], acc[i][j]);
        }
        __syncthreads();
    }

    const int col0 = bcol + tx * 8;
    float4 bi0 = *(const float4*)(bias + col0);
    float4 bi1 = *(const float4*)(bias + col0 + 4);
    const float bb[8] = {bi0.x, bi0.y, bi0.z, bi0.w, bi1.x, bi1.y, bi1.z, bi1.w};

#pragma unroll
    for (int i = 0; i < 8; i++) {
        const int row = brow + ty * 8 + i;
        float4 o0 = make_float4(acc[i][0] + bb[0], acc[i][1] + bb[1],
                                acc[i][2] + bb[2], acc[i][3] + bb[3]);
        float4 o1 = make_float4(acc[i][4] + bb[4], acc[i][5] + bb[5],
                                acc[i][6] + bb[6], acc[i][7] + bb[7]);
        if (MODE == 3) {
            const float4 r0 = *(const float4*)(resid + (size_t)row * N + col0);
            const float4 r1 = *(const float4*)(resid + (size_t)row * N + col0 + 4);
            o0.x += r0.x; o0.y += r0.y; o0.z += r0.z; o0.w += r0.w;
            o1.x += r1.x; o1.y += r1.y; o1.z += r1.z; o1.w += r1.w;
            float* o = g_x + (size_t)row * N + col0;
            *(float4*)o = o0;
            *(float4*)(o + 4) = o1;
        } else {
            float* dst = (MODE == 0) ? g_q : (MODE == 1) ? g_k : g_v;
            const int bidx = row >> 11;          // batch
            const int s    = row & 2047;         // seq pos
            const int hh   = col0 >> 6;          // head
            const int d    = col0 & 63;          // head dim
            float* o = dst + (((size_t)(bidx * NHEAD + hh) * S_LEN) + s) * HD + d;
            *(float4*)o = o0;
            *(float4*)(o + 4) = o1;
        }
    }
}

// ---------------------------------------------------------------------------
// Flash attention, fp32, online softmax. Block = 64 q rows x one (b,h).
// Mask is int32 (bool serialized as int32 by the harness): nonzero = masked.
// ---------------------------------------------------------------------------
__global__ __launch_bounds__(256, 2) void attn_k(const int* __restrict__ mask)
{
    extern __shared__ float sm[];
    float* qs = sm;                 // transposed [d][row], swizzled
    float* ks = qs + 64 * PQ;       // transposed [d][key], swizzled
    float* vs = ks + 64 * PQ;       // [key][d]
    float* ps = vs + 64 * PQ;       // [row][key]

    const int tid = threadIdx.x;
    const int tx = tid & 15;
    const int ty = tid >> 4;
    const int bh = blockIdx.y;
    const int b  = bh >> 4;
    const int h  = bh & 15;
    const int q0 = blockIdx.x * 64;

    const float* qg = g_q + (size_t)bh * S_LEN * HD;
    const float* kg = g_k + (size_t)bh * S_LEN * HD;
    const float* vg = g_v + (size_t)bh * S_LEN * HD;

    // Load q tile transposed, XOR-swizzled (col&28) to tame scatter conflicts.
#pragma unroll
    for (int li = 0; li < 4; li++) {
        int idx = tid + li * 256;
        int r = idx >> 4;
        int c4 = (idx & 15) << 2;
        float4 t = *(const float4*)(qg + (size_t)(q0 + r) * HD + c4);
        qs[(c4 + 0) * PQ + (r ^ ((c4 + 0) & 28))] = t.x;
        qs[(c4 + 1) * PQ + (r ^ ((c4 + 1) & 28))] = t.y;
        qs[(c4 + 2) * PQ + (r ^ ((c4 + 2) & 28))] = t.z;
        qs[(c4 + 3) * PQ + (r ^ ((c4 + 3) & 28))] = t.w;
    }

    float m_i[4], l_i[4], acc[4][4];
#pragma unroll
    for (int i = 0; i < 4; i++) {
        m_i[i] = -INFINITY;
        l_i[i] = 0.f;
#pragma unroll
        for (int j = 0; j < 4; j++) acc[i][j] = 0.f;
    }

    for (int t0 = 0; t0 < 32; t0++) {
        const int k0 = t0 * 64;
        // Load K (transposed+swizzled) and V (row-major) tiles
#pragma unroll
        for (int li = 0; li < 4; li++) {
            int idx = tid + li * 256;
            int r = idx >> 4;
            int c4 = (idx & 15) << 2;
            float4 kt = *(const float4*)(kg + (size_t)(k0 + r) * HD + c4);
            ks[(c4 + 0) * PQ + (r ^ ((c4 + 0) & 28))] = kt.x;
            ks[(c4 + 1) * PQ + (r ^ ((c4 + 1) & 28))] = kt.y;
            ks[(c4 + 2) * PQ + (r ^ ((c4 + 2) & 28))] = kt.z;
            ks[(c4 + 3) * PQ + (r ^ ((c4 + 3) & 28))] = kt.w;
            float4 vt = *(const float4*)(vg + (size_t)(k0 + r) * HD + c4);
            *(float4*)(vs + (size_t)r * PQ + c4) = vt;
        }
        __syncthreads();   // also covers qs on first iteration

        // Scores: s[i][j] = sum_d q[row_i][d] * k[key_j][d]
        float s[4][4];
#pragma unroll
        for (int i = 0; i < 4; i++)
#pragma unroll
            for (int j = 0; j < 4; j++) s[i][j] = 0.f;

#pragma unroll 16
        for (int d = 0; d < 64; d++) {
            const int sw = d & 28;
            float4 qv = *(const float4*)(qs + (size_t)d * PQ + ((ty * 4) ^ sw));
            float4 kv = *(const float4*)(ks + (size_t)d * PQ + ((tx * 4) ^ sw));
            float qa[4] = {qv.x, qv.y, qv.z, qv.w};
            float ka[4] = {kv.x, kv.y, kv.z, kv.w};
#pragma unroll
            for (int i = 0; i < 4; i++)
#pragma unroll
                for (int j = 0; j < 4; j++)
                    s[i][j] = fmaf(qa[i], ka[j], s[i][j]);
        }

        // Scale then mask (exact reference order: mask overrides to -1e9)
        const int* mbase =
            mask + (size_t)b * S_LEN * S_LEN + (size_t)q0 * S_LEN + k0;
#pragma unroll
        for (int i = 0; i < 4; i++) {
            int4 mm = *(const int4*)(mbase + (size_t)(ty * 4 + i) * S_LEN + tx * 4);
            s[i][0] = mm.x ? -1e9f : s[i][0] * 0.125f;
            s[i][1] = mm.y ? -1e9f : s[i][1] * 0.125f;
            s[i][2] = mm.z ? -1e9f : s[i][2] * 0.125f;
            s[i][3] = mm.w ? -1e9f : s[i][3] * 0.125f;
        }

        // Online softmax (row groups = 16 lanes sharing ty)
#pragma unroll
        for (int i = 0; i < 4; i++) {
            float mx = fmaxf(fmaxf(s[i][0], s[i][1]), fmaxf(s[i][2], s[i][3]));
            mx = fmaxf(mx, __shfl_xor_sync(0xffffffffu, mx, 8));
            mx = fmaxf(mx, __shfl_xor_sync(0xffffffffu, mx, 4));
            mx = fmaxf(mx, __shfl_xor_sync(0xffffffffu, mx, 2));
            mx = fmaxf(mx, __shfl_xor_sync(0xffffffffu, mx, 1));
            const float mnew = fmaxf(m_i[i], mx);
            const float corr = __expf(m_i[i] - mnew);
            const float p0 = __expf(s[i][0] - mnew);
            const float p1 = __expf(s[i][1] - mnew);
            const float p2 = __expf(s[i][2] - mnew);
            const float p3 = __expf(s[i][3] - mnew);
            float sum = (p0 + p1) + (p2 + p3);
            sum += __shfl_xor_sync(0xffffffffu, sum, 8);
            sum += __shfl_xor_sync(0xffffffffu, sum, 4);
            sum += __shfl_xor_sync(0xffffffffu, sum, 2);
            sum += __shfl_xor_sync(0xffffffffu, sum, 1);
            l_i[i] = l_i[i] * corr + sum;
            m_i[i] = mnew;
            acc[i][0] *= corr; acc[i][1] *= corr;
            acc[i][2] *= corr; acc[i][3] *= corr;
            float4 pv4 = make_float4(p0, p1, p2, p3);
            *(float4*)(ps + (size_t)(ty * 4 + i) * PQ + tx * 4) = pv4;
        }
        __syncthreads();   // ps visible to all

        // acc += P @ V
#pragma unroll 4
        for (int k4 = 0; k4 < 64; k4 += 4) {
            float prr[4][4];
#pragma unroll
            for (int i = 0; i < 4; i++) {
                float4 p4 = *(const float4*)(ps + (size_t)(ty * 4 + i) * PQ + k4);
                prr[i][0] = p4.x; prr[i][1] = p4.y;
                prr[i][2] = p4.z; prr[i][3] = p4.w;
            }
#pragma unroll
            for (int u = 0; u < 4; u++) {
                float4 vv = *(const float4*)(vs + (size_t)(k4 + u) * PQ + tx * 4);
                float va[4] = {vv.x, vv.y, vv.z, vv.w};
#pragma unroll
                for (int i = 0; i < 4; i++)
#pragma unroll
                    for (int j = 0; j < 4; j++)
                        acc[i][j] = fmaf(prr[i][u], va[j], acc[i][j]);
            }
        }
        __syncthreads();   // protect smem before next tile's loads
    }

    // Epilogue: ctx[b][s][h*64+d] = acc / l
#pragma unroll
    for (int i = 0; i < 4; i++) {
        const float inv = 1.0f / l_i[i];
        const int srow = q0 + ty * 4 + i;
        float4 o = make_float4(acc[i][0] * inv, acc[i][1] * inv,
                               acc[i][2] * inv, acc[i][3] * inv);
        *(float4*)(g_ctx + ((size_t)(b * S_LEN + srow)) * D_DIM + h * HD + tx * 4) = o;
    }
}

// ---------------------------------------------------------------------------
// LayerNorm over last dim (1024), one block per row.
// ---------------------------------------------------------------------------
__global__ __launch_bounds__(256) void ln_k(const float* __restrict__ gamma,
                                            const float* __restrict__ beta,
                                            float* __restrict__ out)
{
    const int row = blockIdx.x;
    const int t = threadIdx.x;
    const float* x = g_x + (size_t)row * D_DIM;
    float4 xv = *(const float4*)(x + t * 4);
    float s  = (xv.x + xv.y) + (xv.z + xv.w);
    float sq = xv.x * xv.x + xv.y * xv.y + xv.z * xv.z + xv.w * xv.w;
#pragma unroll
    for (int off = 16; off; off >>= 1) {
        s  += __shfl_xor_sync(0xffffffffu, s, off);
        sq += __shfl_xor_sync(0xffffffffu, sq, off);
    }
    __shared__ float sh[16];
    const int w = t >> 5;
    if ((t & 31) == 0) { sh[w] = s; sh[8 + w] = sq; }
    __syncthreads();
    float st = 0.f, sqt = 0.f;
#pragma unroll
    for (int i = 0; i < 8; i++) { st += sh[i]; sqt += sh[8 + i]; }
    const float mu   = st * (1.0f / D_DIM);
    const float var  = sqt * (1.0f / D_DIM) - mu * mu;
    const float rstd = rsqrtf(var + 1e-5f);
    float4 g4 = *(const float4*)(gamma + t * 4);
    float4 b4 = *(const float4*)(beta + t * 4);
    float4 o;
    o.x = (xv.x - mu) * rstd * g4.x + b4.x;
    o.y = (xv.y - mu) * rstd * g4.y + b4.y;
    o.z = (xv.z - mu) * rstd * g4.z + b4.z;
    o.w = (xv.w - mu) * rstd * g4.w + b4.w;
    *(float4*)(out + (size_t)row * D_DIM + t * 4) = o;
}

// ---------------------------------------------------------------------------
extern "C" void kernel_launch(void* const* d_in, const int* in_sizes, int n_in,
                              void* d_out, int out_size)
{
    const float* Q   = (const float*)d_in[0];
    const float* Kin = (const float*)d_in[1];
    const float* V   = (const float*)d_in[2];
    const int*   mask = (const int*)d_in[3];
    const float* Wq = (const float*)d_in[4];
    const float* bq = (const float*)d_in[5];
    const float* Wk = (const float*)d_in[6];
    const float* bk = (const float*)d_in[7];
    const float* Wv = (const float*)d_in[8];
    const float* bv = (const float*)d_in[9];
    const float* Wo = (const float*)d_in[10];
    const float* bo = (const float*)d_in[11];
    const float* gamma = (const float*)d_in[12];
    const float* beta  = (const float*)d_in[13];
    float* out = (float*)d_out;

    const int ATTN_SMEM = 4 * 64 * PQ * (int)sizeof(float);
    cudaFuncSetAttribute(attn_k, cudaFuncAttributeMaxDynamicSharedMemorySize, ATTN_SMEM);

    dim3 gg(8, 32);  // (N/128, M/128)
    gemm_k<0><<<gg, 256>>>(Q,   Wq, bq, nullptr);
    gemm_k<1><<<gg, 256>>>(Kin, Wk, bk, nullptr);
    gemm_k<2><<<gg, 256>>>(V,   Wv, bv, nullptr);
    attn_k<<<dim3(32, 32), 256, ATTN_SMEM>>>(mask);
    gemm_k<3><<<gg, 256>>>(nullptr, Wo, bo, Q);
    ln_k<<<4096, 256>>>(gamma, beta, out);
}

// round 4
// speedup vs baseline: 1.2466x; 1.2466x over previous
#include <cuda_runtime.h>
#include <mma.h>
#include <math.h>
#include <cstdint>

using namespace nvcuda;

#define S_LEN 2048
#define D_DIM 1024
#define NHEAD 16
#define HD 64
#define MROWS 4096
#define PSW 72   // padded row width (floats) for attention smem tiles

// Scratch (device globals: no allocations allowed)
__device__ float g_q[MROWS * D_DIM];    // [b,h,s,d]
__device__ float g_k[MROWS * D_DIM];    // [b,h,s,d]
__device__ float g_v[MROWS * D_DIM];    // [b,h,s,d]
__device__ float g_ctx[MROWS * D_DIM];  // [b,s,h*64+d]
__device__ float g_x[MROWS * D_DIM];    // pre-LN

// ===========================================================================
// WMMA tf32 GEMM: C[4096x1024] = A @ W + bias
// CTA tile 128x64, 8 warps of 32x32 (2x2 wmma m16n16k8 tiles each).
// MODE 0/1/2: scatter to g_q/g_k/g_v head layout. MODE 3: + resid -> g_x
// W is consumed row-major [k][n] directly (matrix_b row_major).
// ===========================================================================
#define GEMM_SMEM_FLOATS (128 * 72)          // Cs is the largest alias
#define GEMM_SMEM_BYTES  (GEMM_SMEM_FLOATS * 4)

template <int MODE>
__global__ __launch_bounds__(256) void mm_k(
    const float* __restrict__ A,
    const float* __restrict__ W,
    const float* __restrict__ bias,
    const float* __restrict__ resid)
{
    extern __shared__ float sm[];
    float* As = sm;            // 128 x 40 (5120 floats)
    float* Bs = sm + 5120;     // 32 x 72  (2304 floats)
    float* Cs = sm;            // 128 x 72 (aliased after mainloop)

    const int tid = threadIdx.x;
    const int wid = tid >> 5;
    const int wr = wid >> 1;          // warp row 0..3 -> m offset wr*32
    const int wc = wid & 1;           // warp col 0..1 -> n offset wc*32
    const int brow = blockIdx.y * 128;
    const int bcol = blockIdx.x * 64;

    const float* Ap = (MODE == 3) ? (const float*)g_ctx : A;

    wmma::fragment<wmma::accumulator, 16, 16, 8, float> acc[2][2];
#pragma unroll
    for (int mi = 0; mi < 2; mi++)
#pragma unroll
        for (int ni = 0; ni < 2; ni++)
            wmma::fill_fragment(acc[mi][ni], 0.0f);

    for (int kc = 0; kc < D_DIM; kc += 32) {
        // Load A tile 128x32 and B tile 32x64
#pragma unroll
        for (int j = 0; j < 4; j++) {
            const int lin = tid + j * 256;        // float4 index, 1024 total
            const int r = lin >> 3;
            const int c4 = (lin & 7) << 2;
            *(float4*)&As[r * 40 + c4] =
                *(const float4*)(Ap + (size_t)(brow + r) * D_DIM + kc + c4);
        }
#pragma unroll
        for (int j = 0; j < 2; j++) {
            const int lin = tid + j * 256;        // float4 index, 512 total
            const int r = lin >> 4;
            const int c4 = (lin & 15) << 2;
            *(float4*)&Bs[r * 72 + c4] =
                *(const float4*)(W + (size_t)(kc + r) * D_DIM + bcol + c4);
        }
        __syncthreads();

#pragma unroll
        for (int k0 = 0; k0 < 32; k0 += 8) {
            wmma::fragment<wmma::matrix_a, 16, 16, 8, wmma::precision::tf32,
                           wmma::row_major> af[2];
            wmma::fragment<wmma::matrix_b, 16, 16, 8, wmma::precision::tf32,
                           wmma::row_major> bf[2];
#pragma unroll
            for (int mi = 0; mi < 2; mi++) {
                wmma::load_matrix_sync(af[mi], &As[(wr * 32 + mi * 16) * 40 + k0], 40);
#pragma unroll
                for (int e = 0; e < af[mi].num_elements; e++)
                    af[mi].x[e] = wmma::__float_to_tf32(af[mi].x[e]);
            }
#pragma unroll
            for (int ni = 0; ni < 2; ni++) {
                wmma::load_matrix_sync(bf[ni], &Bs[k0 * 72 + wc * 32 + ni * 16], 72);
#pragma unroll
                for (int e = 0; e < bf[ni].num_elements; e++)
                    bf[ni].x[e] = wmma::__float_to_tf32(bf[ni].x[e]);
            }
#pragma unroll
            for (int mi = 0; mi < 2; mi++)
#pragma unroll
                for (int ni = 0; ni < 2; ni++)
                    wmma::mma_sync(acc[mi][ni], af[mi], bf[ni], acc[mi][ni]);
        }
        __syncthreads();
    }

    // Store accumulators to smem (aliases As/Bs — loop ended with sync)
#pragma unroll
    for (int mi = 0; mi < 2; mi++)
#pragma unroll
        for (int ni = 0; ni < 2; ni++)
            wmma::store_matrix_sync(&Cs[(wr * 32 + mi * 16) * 72 + wc * 32 + ni * 16],
                                    acc[mi][ni], 72, wmma::mem_row_major);
    __syncthreads();

    // Scalar epilogue: bias (+ residual) + scatter
#pragma unroll
    for (int j = 0; j < 8; j++) {
        const int lin = tid + j * 256;            // float4 index, 2048 total
        const int r = lin >> 4;
        const int c4 = (lin & 15) << 2;
        const int row = brow + r;
        const int col = bcol + c4;
        float4 cv = *(float4*)&Cs[r * 72 + c4];
        const float4 bi = *(const float4*)(bias + col);
        cv.x += bi.x; cv.y += bi.y; cv.z += bi.z; cv.w += bi.w;
        if (MODE == 3) {
            const float4 rv = *(const float4*)(resid + (size_t)row * D_DIM + col);
            cv.x += rv.x; cv.y += rv.y; cv.z += rv.z; cv.w += rv.w;
            *(float4*)(g_x + (size_t)row * D_DIM + col) = cv;
        } else {
            float* dst = (MODE == 0) ? g_q : (MODE == 1) ? g_k : g_v;
            const int bidx = row >> 11;
            const int sPos = row & 2047;
            const int hh = col >> 6;
            const int d = col & 63;
            *(float4*)(dst + (((size_t)(bidx * NHEAD + hh) * S_LEN) + sPos) * HD + d) = cv;
        }
    }
}

// ===========================================================================
// Flash attention with WMMA tf32 for QK^T and P@V; scalar online softmax.
// Block = 64 q rows x one (b,h), 256 threads = 8 warps.
// Mask is int32 (bool serialized as int32): nonzero = masked.
// ===========================================================================
#define ATTN_SMEM_FLOATS (5 * 64 * PSW)
#define ATTN_SMEM_BYTES  (ATTN_SMEM_FLOATS * 4)

__global__ __launch_bounds__(256) void attn_k(const int* __restrict__ mask)
{
    extern __shared__ float sm[];
    float* qs = sm;                  // [64][PSW] Q tile, row-major
    float* ks = sm + 64 * PSW;       // [64][PSW] K tile, row-major [key][d]
    float* vs = sm + 2 * 64 * PSW;   // [64][PSW] V tile, row-major [key][d]
    float* ps = sm + 3 * 64 * PSW;   // [64][PSW] scores / probabilities
    float* ov = sm + 4 * 64 * PSW;   // [64][PSW] per-tile PV output

    const int tid = threadIdx.x;
    const int wid = tid >> 5;
    const int tx = tid & 15;
    const int ty = tid >> 4;
    const int bh = blockIdx.y;
    const int b  = bh >> 4;
    const int q0 = blockIdx.x * 64;
    const int h  = bh & 15;

    const float* qg = g_q + (size_t)bh * S_LEN * HD;
    const float* kg = g_k + (size_t)bh * S_LEN * HD;
    const float* vg = g_v + (size_t)bh * S_LEN * HD;

    // Warp tile assignment for 64x64 output: 4x4 tiles of 16x16, 2 per warp
    const int wm0 = (wid >> 1) * 16;          // m tile offset
    const int wn_base = (wid & 1) * 32;       // two n tiles at wn_base, wn_base+16

    // Load Q tile (row-major, padded)
#pragma unroll
    for (int j = 0; j < 4; j++) {
        const int lin = tid + j * 256;        // 1024 float4s
        const int r = lin >> 4;
        const int c4 = (lin & 15) << 2;
        *(float4*)&qs[r * PSW + c4] =
            *(const float4*)(qg + (size_t)(q0 + r) * HD + c4);
    }

    float m_i[4], l_i[4], acc[4][4];
#pragma unroll
    for (int i = 0; i < 4; i++) {
        m_i[i] = -INFINITY;
        l_i[i] = 0.f;
#pragma unroll
        for (int j = 0; j < 4; j++) acc[i][j] = 0.f;
    }

    for (int t0 = 0; t0 < 32; t0++) {
        const int k0g = t0 * 64;
        // Load K and V tiles (row-major)
#pragma unroll
        for (int j = 0; j < 4; j++) {
            const int lin = tid + j * 256;
            const int r = lin >> 4;
            const int c4 = (lin & 15) << 2;
            *(float4*)&ks[r * PSW + c4] =
                *(const float4*)(kg + (size_t)(k0g + r) * HD + c4);
            *(float4*)&vs[r * PSW + c4] =
                *(const float4*)(vg + (size_t)(k0g + r) * HD + c4);
        }
        __syncthreads();   // (A) tiles ready; also covers qs on iter 0

        // ---- S = Q @ K^T via wmma ----
        {
            wmma::fragment<wmma::accumulator, 16, 16, 8, float> sfrag[2];
            wmma::fill_fragment(sfrag[0], 0.0f);
            wmma::fill_fragment(sfrag[1], 0.0f);
#pragma unroll
            for (int k0 = 0; k0 < 64; k0 += 8) {
                wmma::fragment<wmma::matrix_a, 16, 16, 8, wmma::precision::tf32,
                               wmma::row_major> af;
                wmma::load_matrix_sync(af, &qs[wm0 * PSW + k0], PSW);
#pragma unroll
                for (int e = 0; e < af.num_elements; e++)
                    af.x[e] = wmma::__float_to_tf32(af.x[e]);
#pragma unroll
                for (int cc = 0; cc < 2; cc++) {
                    // B = K^T: element (k,n) at ks[n][k] -> col_major, ld=PSW
                    wmma::fragment<wmma::matrix_b, 16, 16, 8, wmma::precision::tf32,
                                   wmma::col_major> bf;
                    wmma::load_matrix_sync(bf, &ks[(wn_base + cc * 16) * PSW + k0], PSW);
#pragma unroll
                    for (int e = 0; e < bf.num_elements; e++)
                        bf.x[e] = wmma::__float_to_tf32(bf.x[e]);
                    wmma::mma_sync(sfrag[cc], af, bf, sfrag[cc]);
                }
            }
#pragma unroll
            for (int cc = 0; cc < 2; cc++)
                wmma::store_matrix_sync(&ps[wm0 * PSW + wn_base + cc * 16],
                                        sfrag[cc], PSW, wmma::mem_row_major);
        }
        __syncthreads();   // (B) scores in ps

        // ---- scalar: scale, mask, online softmax; write P back to ps ----
        const int* mbase =
            mask + (size_t)b * S_LEN * S_LEN + (size_t)q0 * S_LEN + k0g;
#pragma unroll
        for (int i = 0; i < 4; i++) {
            const int row = ty * 4 + i;
            const int4 mm = *(const int4*)(mbase + (size_t)row * S_LEN + tx * 4);
            const float4 sv = *(const float4*)&ps[row * PSW + tx * 4];
            float s0 = mm.x ? -1e9f : sv.x * 0.125f;
            float s1 = mm.y ? -1e9f : sv.y * 0.125f;
            float s2 = mm.z ? -1e9f : sv.z * 0.125f;
            float s3 = mm.w ? -1e9f : sv.w * 0.125f;

            float mx = fmaxf(fmaxf(s0, s1), fmaxf(s2, s3));
            mx = fmaxf(mx, __shfl_xor_sync(0xffffffffu, mx, 8));
            mx = fmaxf(mx, __shfl_xor_sync(0xffffffffu, mx, 4));
            mx = fmaxf(mx, __shfl_xor_sync(0xffffffffu, mx, 2));
            mx = fmaxf(mx, __shfl_xor_sync(0xffffffffu, mx, 1));
            const float mnew = fmaxf(m_i[i], mx);
            const float corr = __expf(m_i[i] - mnew);
            const float p0 = __expf(s0 - mnew);
            const float p1 = __expf(s1 - mnew);
            const float p2 = __expf(s2 - mnew);
            const float p3 = __expf(s3 - mnew);
            float sum = (p0 + p1) + (p2 + p3);
            sum += __shfl_xor_sync(0xffffffffu, sum, 8);
            sum += __shfl_xor_sync(0xffffffffu, sum, 4);
            sum += __shfl_xor_sync(0xffffffffu, sum, 2);
            sum += __shfl_xor_sync(0xffffffffu, sum, 1);
            l_i[i] = l_i[i] * corr + sum;
            m_i[i] = mnew;
            acc[i][0] *= corr; acc[i][1] *= corr;
            acc[i][2] *= corr; acc[i][3] *= corr;
            *(float4*)&ps[row * PSW + tx * 4] = make_float4(p0, p1, p2, p3);
        }
        __syncthreads();   // (C) P ready in ps

        // ---- O_tile = P @ V via wmma ----
        {
            wmma::fragment<wmma::accumulator, 16, 16, 8, float> ofrag[2];
            wmma::fill_fragment(ofrag[0], 0.0f);
            wmma::fill_fragment(ofrag[1], 0.0f);
#pragma unroll
            for (int k0 = 0; k0 < 64; k0 += 8) {
                wmma::fragment<wmma::matrix_a, 16, 16, 8, wmma::precision::tf32,
                               wmma::row_major> af;
                wmma::load_matrix_sync(af, &ps[wm0 * PSW + k0], PSW);
#pragma unroll
                for (int e = 0; e < af.num_elements; e++)
                    af.x[e] = wmma::__float_to_tf32(af.x[e]);
#pragma unroll
                for (int cc = 0; cc < 2; cc++) {
                    wmma::fragment<wmma::matrix_b, 16, 16, 8, wmma::precision::tf32,
                                   wmma::row_major> bf;
                    wmma::load_matrix_sync(bf, &vs[k0 * PSW + wn_base + cc * 16], PSW);
#pragma unroll
                    for (int e = 0; e < bf.num_elements; e++)
                        bf.x[e] = wmma::__float_to_tf32(bf.x[e]);
                    wmma::mma_sync(ofrag[cc], af, bf, ofrag[cc]);
                }
            }
#pragma unroll
            for (int cc = 0; cc < 2; cc++)
                wmma::store_matrix_sync(&ov[wm0 * PSW + wn_base + cc * 16],
                                        ofrag[cc], PSW, wmma::mem_row_major);
        }
        __syncthreads();   // (D) ov ready

        // ---- scalar: accumulate ov into registers ----
#pragma unroll
        for (int i = 0; i < 4; i++) {
            const int row = ty * 4 + i;
            const float4 o4 = *(const float4*)&ov[row * PSW + tx * 4];
            acc[i][0] += o4.x; acc[i][1] += o4.y;
            acc[i][2] += o4.z; acc[i][3] += o4.w;
        }
        __syncthreads();   // protect ks/vs/ps/ov before next iteration
    }

    // Epilogue: ctx[b][s][h*64+d] = acc / l
#pragma unroll
    for (int i = 0; i < 4; i++) {
        const float inv = 1.0f / l_i[i];
        const int srow = q0 + ty * 4 + i;
        float4 o = make_float4(acc[i][0] * inv, acc[i][1] * inv,
                               acc[i][2] * inv, acc[i][3] * inv);
        *(float4*)(g_ctx + ((size_t)(b * S_LEN + srow)) * D_DIM + h * HD + tx * 4) = o;
    }
}

// ---------------------------------------------------------------------------
// LayerNorm over last dim (1024), one block per row.
// ---------------------------------------------------------------------------
__global__ __launch_bounds__(256) void ln_k(const float* __restrict__ gamma,
                                            const float* __restrict__ beta,
                                            float* __restrict__ out)
{
    const int row = blockIdx.x;
    const int t = threadIdx.x;
    const float* x = g_x + (size_t)row * D_DIM;
    float4 xv = *(const float4*)(x + t * 4);
    float s  = (xv.x + xv.y) + (xv.z + xv.w);
    float sq = xv.x * xv.x + xv.y * xv.y + xv.z * xv.z + xv.w * xv.w;
#pragma unroll
    for (int off = 16; off; off >>= 1) {
        s  += __shfl_xor_sync(0xffffffffu, s, off);
        sq += __shfl_xor_sync(0xffffffffu, sq, off);
    }
    __shared__ float sh[16];
    const int w = t >> 5;
    if ((t & 31) == 0) { sh[w] = s; sh[8 + w] = sq; }
    __syncthreads();
    float st = 0.f, sqt = 0.f;
#pragma unroll
    for (int i = 0; i < 8; i++) { st += sh[i]; sqt += sh[8 + i]; }
    const float mu   = st * (1.0f / D_DIM);
    const float var  = sqt * (1.0f / D_DIM) - mu * mu;
    const float rstd = rsqrtf(var + 1e-5f);
    float4 g4 = *(const float4*)(gamma + t * 4);
    float4 b4 = *(const float4*)(beta + t * 4);
    float4 o;
    o.x = (xv.x - mu) * rstd * g4.x + b4.x;
    o.y = (xv.y - mu) * rstd * g4.y + b4.y;
    o.z = (xv.z - mu) * rstd * g4.z + b4.z;
    o.w = (xv.w - mu) * rstd * g4.w + b4.w;
    *(float4*)(out + (size_t)row * D_DIM + t * 4) = o;
}

// ---------------------------------------------------------------------------
extern "C" void kernel_launch(void* const* d_in, const int* in_sizes, int n_in,
                              void* d_out, int out_size)
{
    const float* Q   = (const float*)d_in[0];
    const float* Kin = (const float*)d_in[1];
    const float* V   = (const float*)d_in[2];
    const int*   mask = (const int*)d_in[3];
    const float* Wq = (const float*)d_in[4];
    const float* bq = (const float*)d_in[5];
    const float* Wk = (const float*)d_in[6];
    const float* bk = (const float*)d_in[7];
    const float* Wv = (const float*)d_in[8];
    const float* bv = (const float*)d_in[9];
    const float* Wo = (const float*)d_in[10];
    const float* bo = (const float*)d_in[11];
    const float* gamma = (const float*)d_in[12];
    const float* beta  = (const float*)d_in[13];
    float* out = (float*)d_out;

    cudaFuncSetAttribute(attn_k, cudaFuncAttributeMaxDynamicSharedMemorySize, ATTN_SMEM_BYTES);

    dim3 gg(16, 32);  // (N/64, M/128)
    mm_k<0><<<gg, 256, GEMM_SMEM_BYTES>>>(Q,   Wq, bq, nullptr);
    mm_k<1><<<gg, 256, GEMM_SMEM_BYTES>>>(Kin, Wk, bk, nullptr);
    mm_k<2><<<gg, 256, GEMM_SMEM_BYTES>>>(V,   Wv, bv, nullptr);
    attn_k<<<dim3(32, 32), 256, ATTN_SMEM_BYTES>>>(mask);
    mm_k<3><<<gg, 256, GEMM_SMEM_BYTES>>>(nullptr, Wo, bo, Q);
    ln_k<<<4096, 256>>>(gamma, beta, out);
}

// round 5
// speedup vs baseline: 1.6854x; 1.3520x over previous
#include <cuda_runtime.h>
#include <mma.h>
#include <math.h>
#include <cstdint>

using namespace nvcuda;

#define S_LEN 2048
#define D_DIM 1024
#define NHEAD 16
#define HD 64
#define MROWS 4096
#define PSW 72   // padded row width for GEMM smem
#define APW 68   // padded row width for attention smem tiles

// Scratch (device globals: no allocations allowed)
__device__ float g_q[MROWS * D_DIM];    // [b,h,s,d]
__device__ float g_k[MROWS * D_DIM];    // [b,h,s,d]
__device__ float g_v[MROWS * D_DIM];    // [b,h,s,d]
__device__ float g_ctx[MROWS * D_DIM];  // [b,s,h*64+d]
__device__ float g_x[MROWS * D_DIM];    // pre-LN

__device__ __forceinline__ uint32_t f2tf32(float f) {
    uint32_t r;
    asm("cvt.rna.tf32.f32 %0, %1;" : "=r"(r) : "f"(f));
    return r;
}
__device__ __forceinline__ float f2tf32f(float f) {
    return __uint_as_float(f2tf32(f));
}

// mma.m16n8k8 tf32: D += A(16x8,row) * B(8x8,col)
__device__ __forceinline__ void mma8(float& d0, float& d1, float& d2, float& d3,
                                     uint32_t a0, uint32_t a1, uint32_t a2, uint32_t a3,
                                     uint32_t b0, uint32_t b1)
{
    asm volatile(
        "mma.sync.aligned.m16n8k8.row.col.f32.tf32.tf32.f32 "
        "{%0,%1,%2,%3}, {%4,%5,%6,%7}, {%8,%9}, {%0,%1,%2,%3};"
        : "+f"(d0), "+f"(d1), "+f"(d2), "+f"(d3)
        : "r"(a0), "r"(a1), "r"(a2), "r"(a3), "r"(b0), "r"(b1));
}

// ===========================================================================
// WMMA tf32 GEMM: C[4096x1024] = A @ W + bias (tf32 conversion done at fill)
// CTA tile 128x64, 8 warps of 32x32. MODE 0/1/2 scatter head layout; 3 resid.
// ===========================================================================
#define GEMM_SMEM_FLOATS (128 * 72)
#define GEMM_SMEM_BYTES  (GEMM_SMEM_FLOATS * 4)

template <int MODE>
__global__ __launch_bounds__(256) void mm_k(
    const float* __restrict__ A,
    const float* __restrict__ W,
    const float* __restrict__ bias,
    const float* __restrict__ resid)
{
    extern __shared__ float sm[];
    float* As = sm;            // 128 x 40
    float* Bs = sm + 5120;     // 32 x 72
    float* Cs = sm;            // 128 x 72 (alias)

    const int tid = threadIdx.x;
    const int wid = tid >> 5;
    const int wr = wid >> 1;
    const int wc = wid & 1;
    const int brow = blockIdx.y * 128;
    const int bcol = blockIdx.x * 64;

    const float* Ap = (MODE == 3) ? (const float*)g_ctx : A;

    wmma::fragment<wmma::accumulator, 16, 16, 8, float> acc[2][2];
#pragma unroll
    for (int mi = 0; mi < 2; mi++)
#pragma unroll
        for (int ni = 0; ni < 2; ni++)
            wmma::fill_fragment(acc[mi][ni], 0.0f);

    for (int kc = 0; kc < D_DIM; kc += 32) {
#pragma unroll
        for (int j = 0; j < 4; j++) {
            const int lin = tid + j * 256;
            const int r = lin >> 3;
            const int c4 = (lin & 7) << 2;
            float4 av = *(const float4*)(Ap + (size_t)(brow + r) * D_DIM + kc + c4);
            av.x = f2tf32f(av.x); av.y = f2tf32f(av.y);
            av.z = f2tf32f(av.z); av.w = f2tf32f(av.w);
            *(float4*)&As[r * 40 + c4] = av;
        }
#pragma unroll
        for (int j = 0; j < 2; j++) {
            const int lin = tid + j * 256;
            const int r = lin >> 4;
            const int c4 = (lin & 15) << 2;
            float4 bv = *(const float4*)(W + (size_t)(kc + r) * D_DIM + bcol + c4);
            bv.x = f2tf32f(bv.x); bv.y = f2tf32f(bv.y);
            bv.z = f2tf32f(bv.z); bv.w = f2tf32f(bv.w);
            *(float4*)&Bs[r * 72 + c4] = bv;
        }
        __syncthreads();

#pragma unroll
        for (int k0 = 0; k0 < 32; k0 += 8) {
            wmma::fragment<wmma::matrix_a, 16, 16, 8, wmma::precision::tf32,
                           wmma::row_major> af[2];
            wmma::fragment<wmma::matrix_b, 16, 16, 8, wmma::precision::tf32,
                           wmma::row_major> bf[2];
#pragma unroll
            for (int mi = 0; mi < 2; mi++)
                wmma::load_matrix_sync(af[mi], &As[(wr * 32 + mi * 16) * 40 + k0], 40);
#pragma unroll
            for (int ni = 0; ni < 2; ni++)
                wmma::load_matrix_sync(bf[ni], &Bs[k0 * 72 + wc * 32 + ni * 16], 72);
#pragma unroll
            for (int mi = 0; mi < 2; mi++)
#pragma unroll
                for (int ni = 0; ni < 2; ni++)
                    wmma::mma_sync(acc[mi][ni], af[mi], bf[ni], acc[mi][ni]);
        }
        __syncthreads();
    }

#pragma unroll
    for (int mi = 0; mi < 2; mi++)
#pragma unroll
        for (int ni = 0; ni < 2; ni++)
            wmma::store_matrix_sync(&Cs[(wr * 32 + mi * 16) * 72 + wc * 32 + ni * 16],
                                    acc[mi][ni], 72, wmma::mem_row_major);
    __syncthreads();

#pragma unroll
    for (int j = 0; j < 8; j++) {
        const int lin = tid + j * 256;
        const int r = lin >> 4;
        const int c4 = (lin & 15) << 2;
        const int row = brow + r;
        const int col = bcol + c4;
        float4 cv = *(float4*)&Cs[r * 72 + c4];
        const float4 bi = *(const float4*)(bias + col);
        cv.x += bi.x; cv.y += bi.y; cv.z += bi.z; cv.w += bi.w;
        if (MODE == 3) {
            const float4 rv = *(const float4*)(resid + (size_t)row * D_DIM + col);
            cv.x += rv.x; cv.y += rv.y; cv.z += rv.z; cv.w += rv.w;
            *(float4*)(g_x + (size_t)row * D_DIM + col) = cv;
        } else {
            float* dst = (MODE == 0) ? g_q : (MODE == 1) ? g_k : g_v;
            const int bidx = row >> 11;
            const int sPos = row & 2047;
            const int hh = col >> 6;
            const int d = col & 63;
            *(float4*)(dst + (((size_t)(bidx * NHEAD + hh) * S_LEN) + sPos) * HD + d) = cv;
        }
    }
}

// ===========================================================================
// Flash attention, raw mma.m16n8k8 tf32, fully register-resident.
// CTA = 128 q rows x one (b,h); 8 warps, warp owns 16 q rows x 64-wide KV tile.
// Q fragments pinned in regs for all KV tiles; softmax + P->Afrag via quad
// shuffles on the documented accumulator layout; O persistent in registers.
// Mask is int32 (bool serialized as int32): nonzero = masked.
// ===========================================================================
#define ATTN_SMEM_FLOATS (128 * APW + 2 * 64 * APW)
#define ATTN_SMEM_BYTES  (ATTN_SMEM_FLOATS * 4)

__global__ __launch_bounds__(256) void attn_k(const int* __restrict__ mask)
{
    extern __shared__ float sm[];
    float* qs = sm;                   // [128][APW]
    float* ks = sm + 128 * APW;       // [64][APW]  K tile [key][d]
    float* vs = sm + 192 * APW;       // [64][APW]  V tile [key][d]

    const int tid = threadIdx.x;
    const int lane = tid & 31;
    const int wid = tid >> 5;
    const int g = lane >> 2;          // groupID 0..7
    const int t = lane & 3;           // threadInGroup 0..3
    const int qbase = lane & ~3;      // quad leader lane

    const int bh = blockIdx.y;
    const int b = bh >> 4;
    const int h = bh & 15;
    const int q0 = blockIdx.x * 128;

    const float* qg = g_q + (size_t)bh * S_LEN * HD;
    const float* kg = g_k + (size_t)bh * S_LEN * HD;
    const float* vg = g_v + (size_t)bh * S_LEN * HD;

    // ---- load Q tile (convert to tf32 at fill) ----
#pragma unroll
    for (int j = 0; j < 8; j++) {
        const int lin = tid + j * 256;          // 2048 float4s
        const int r = lin >> 4;
        const int c4 = (lin & 15) << 2;
        float4 qv = *(const float4*)(qg + (size_t)(q0 + r) * HD + c4);
        qv.x = f2tf32f(qv.x); qv.y = f2tf32f(qv.y);
        qv.z = f2tf32f(qv.z); qv.w = f2tf32f(qv.w);
        *(float4*)&qs[r * APW + c4] = qv;
    }
    __syncthreads();

    // ---- Q fragments pinned in registers: 8 k-steps x 4 regs ----
    const int wrow = wid * 16;
    uint32_t qa[8][4];
#pragma unroll
    for (int s = 0; s < 8; s++) {
        qa[s][0] = __float_as_uint(qs[(wrow + g) * APW + s * 8 + t]);
        qa[s][1] = __float_as_uint(qs[(wrow + g + 8) * APW + s * 8 + t]);
        qa[s][2] = __float_as_uint(qs[(wrow + g) * APW + s * 8 + t + 4]);
        qa[s][3] = __float_as_uint(qs[(wrow + g + 8) * APW + s * 8 + t + 4]);
    }

    float o[8][4];
#pragma unroll
    for (int nt = 0; nt < 8; nt++)
#pragma unroll
        for (int e = 0; e < 4; e++) o[nt][e] = 0.f;
    float m0 = -INFINITY, m1 = -INFINITY, l0 = 0.f, l1 = 0.f;

    const int row0 = q0 + wrow + g;
    const int row1 = row0 + 8;
    const int* mrow0 = mask + (size_t)b * S_LEN * S_LEN + (size_t)row0 * S_LEN;
    const int* mrow1 = mask + (size_t)b * S_LEN * S_LEN + (size_t)row1 * S_LEN;

    for (int t0 = 0; t0 < 32; t0++) {
        const int k0g = t0 * 64;
        if (t0 > 0) __syncthreads();   // protect smem from prev iter readers

        // ---- cooperative K/V tile load (tf32 at fill) ----
#pragma unroll
        for (int j = 0; j < 4; j++) {
            const int lin = tid + j * 256;      // 1024 float4s
            const int r = lin >> 4;
            const int c4 = (lin & 15) << 2;
            float4 kv = *(const float4*)(kg + (size_t)(k0g + r) * HD + c4);
            kv.x = f2tf32f(kv.x); kv.y = f2tf32f(kv.y);
            kv.z = f2tf32f(kv.z); kv.w = f2tf32f(kv.w);
            *(float4*)&ks[r * APW + c4] = kv;
            float4 vv = *(const float4*)(vg + (size_t)(k0g + r) * HD + c4);
            vv.x = f2tf32f(vv.x); vv.y = f2tf32f(vv.y);
            vv.z = f2tf32f(vv.z); vv.w = f2tf32f(vv.w);
            *(float4*)&vs[r * APW + c4] = vv;
        }
        __syncthreads();

        // ---- S = Q K^T : 8 n-tiles x 8 k-steps ----
        float sacc[8][4];
#pragma unroll
        for (int nt = 0; nt < 8; nt++) {
            sacc[nt][0] = 0.f; sacc[nt][1] = 0.f;
            sacc[nt][2] = 0.f; sacc[nt][3] = 0.f;
            const float* kb = &ks[(nt * 8 + g) * APW];
#pragma unroll
            for (int s = 0; s < 8; s++) {
                const uint32_t b0 = __float_as_uint(kb[s * 8 + t]);
                const uint32_t b1 = __float_as_uint(kb[s * 8 + t + 4]);
                mma8(sacc[nt][0], sacc[nt][1], sacc[nt][2], sacc[nt][3],
                     qa[s][0], qa[s][1], qa[s][2], qa[s][3], b0, b1);
            }
        }

        // ---- scale + mask ----
#pragma unroll
        for (int nt = 0; nt < 8; nt++) {
            const int cpos = k0g + nt * 8 + 2 * t;
            const int2 mv0 = *(const int2*)(mrow0 + cpos);
            const int2 mv1 = *(const int2*)(mrow1 + cpos);
            sacc[nt][0] = mv0.x ? -1e9f : sacc[nt][0] * 0.125f;
            sacc[nt][1] = mv0.y ? -1e9f : sacc[nt][1] * 0.125f;
            sacc[nt][2] = mv1.x ? -1e9f : sacc[nt][2] * 0.125f;
            sacc[nt][3] = mv1.y ? -1e9f : sacc[nt][3] * 0.125f;
        }

        // ---- online softmax on the accumulator layout ----
        float mx0 = -INFINITY, mx1 = -INFINITY;
#pragma unroll
        for (int nt = 0; nt < 8; nt++) {
            mx0 = fmaxf(mx0, fmaxf(sacc[nt][0], sacc[nt][1]));
            mx1 = fmaxf(mx1, fmaxf(sacc[nt][2], sacc[nt][3]));
        }
        mx0 = fmaxf(mx0, __shfl_xor_sync(0xffffffffu, mx0, 1));
        mx0 = fmaxf(mx0, __shfl_xor_sync(0xffffffffu, mx0, 2));
        mx1 = fmaxf(mx1, __shfl_xor_sync(0xffffffffu, mx1, 1));
        mx1 = fmaxf(mx1, __shfl_xor_sync(0xffffffffu, mx1, 2));
        const float mn0 = fmaxf(m0, mx0);
        const float mn1 = fmaxf(m1, mx1);
        const float cr0 = __expf(m0 - mn0);
        const float cr1 = __expf(m1 - mn1);
        float sum0 = 0.f, sum1 = 0.f;
#pragma unroll
        for (int nt = 0; nt < 8; nt++) {
            sacc[nt][0] = __expf(sacc[nt][0] - mn0);
            sacc[nt][1] = __expf(sacc[nt][1] - mn0);
            sacc[nt][2] = __expf(sacc[nt][2] - mn1);
            sacc[nt][3] = __expf(sacc[nt][3] - mn1);
            sum0 += sacc[nt][0] + sacc[nt][1];
            sum1 += sacc[nt][2] + sacc[nt][3];
        }
        sum0 += __shfl_xor_sync(0xffffffffu, sum0, 1);
        sum0 += __shfl_xor_sync(0xffffffffu, sum0, 2);
        sum1 += __shfl_xor_sync(0xffffffffu, sum1, 1);
        sum1 += __shfl_xor_sync(0xffffffffu, sum1, 2);
        l0 = l0 * cr0 + sum0;
        l1 = l1 * cr1 + sum1;
        m0 = mn0; m1 = mn1;

        // rescale O, convert P to tf32 in place
#pragma unroll
        for (int nt = 0; nt < 8; nt++) {
            o[nt][0] *= cr0; o[nt][1] *= cr0;
            o[nt][2] *= cr1; o[nt][3] *= cr1;
            sacc[nt][0] = __uint_as_float(f2tf32(sacc[nt][0]));
            sacc[nt][1] = __uint_as_float(f2tf32(sacc[nt][1]));
            sacc[nt][2] = __uint_as_float(f2tf32(sacc[nt][2]));
            sacc[nt][3] = __uint_as_float(f2tf32(sacc[nt][3]));
        }

        // ---- O += P V : per k-step build A frag from P via quad shuffles ----
#pragma unroll
        for (int s = 0; s < 8; s++) {
            const uint32_t p0 = __float_as_uint(sacc[s][0]);
            const uint32_t p1 = __float_as_uint(sacc[s][1]);
            const uint32_t p2 = __float_as_uint(sacc[s][2]);
            const uint32_t p3 = __float_as_uint(sacc[s][3]);
            const int lo = qbase + (t >> 1);
            const int hi = lo + 2;
            const uint32_t x0 = __shfl_sync(0xffffffffu, p0, lo);
            const uint32_t x1 = __shfl_sync(0xffffffffu, p1, lo);
            const uint32_t x2 = __shfl_sync(0xffffffffu, p0, hi);
            const uint32_t x3 = __shfl_sync(0xffffffffu, p1, hi);
            const uint32_t y0 = __shfl_sync(0xffffffffu, p2, lo);
            const uint32_t y1 = __shfl_sync(0xffffffffu, p3, lo);
            const uint32_t y2 = __shfl_sync(0xffffffffu, p2, hi);
            const uint32_t y3 = __shfl_sync(0xffffffffu, p3, hi);
            const uint32_t a0 = (t & 1) ? x1 : x0;
            const uint32_t a2 = (t & 1) ? x3 : x2;
            const uint32_t a1 = (t & 1) ? y1 : y0;
            const uint32_t a3 = (t & 1) ? y3 : y2;
            const float* vb = &vs[(s * 8 + t) * APW];
            const float* vb4 = &vs[(s * 8 + t + 4) * APW];
#pragma unroll
            for (int nt = 0; nt < 8; nt++) {
                const uint32_t b0 = __float_as_uint(vb[nt * 8 + g]);
                const uint32_t b1 = __float_as_uint(vb4[nt * 8 + g]);
                mma8(o[nt][0], o[nt][1], o[nt][2], o[nt][3],
                     a0, a1, a2, a3, b0, b1);
            }
        }
    }

    // ---- epilogue: ctx[b][s][h*64+d] = O / l ----
    const float inv0 = 1.0f / l0;
    const float inv1 = 1.0f / l1;
#pragma unroll
    for (int nt = 0; nt < 8; nt++) {
        const int col = h * 64 + nt * 8 + 2 * t;
        *(float2*)(g_ctx + (size_t)(b * S_LEN + row0) * D_DIM + col) =
            make_float2(o[nt][0] * inv0, o[nt][1] * inv0);
        *(float2*)(g_ctx + (size_t)(b * S_LEN + row1) * D_DIM + col) =
            make_float2(o[nt][2] * inv1, o[nt][3] * inv1);
    }
}

// ---------------------------------------------------------------------------
// LayerNorm over last dim (1024), one block per row.
// ---------------------------------------------------------------------------
__global__ __launch_bounds__(256) void ln_k(const float* __restrict__ gamma,
                                            const float* __restrict__ beta,
                                            float* __restrict__ out)
{
    const int row = blockIdx.x;
    const int t = threadIdx.x;
    const float* x = g_x + (size_t)row * D_DIM;
    float4 xv = *(const float4*)(x + t * 4);
    float s  = (xv.x + xv.y) + (xv.z + xv.w);
    float sq = xv.x * xv.x + xv.y * xv.y + xv.z * xv.z + xv.w * xv.w;
#pragma unroll
    for (int off = 16; off; off >>= 1) {
        s  += __shfl_xor_sync(0xffffffffu, s, off);
        sq += __shfl_xor_sync(0xffffffffu, sq, off);
    }
    __shared__ float sh[16];
    const int w = t >> 5;
    if ((t & 31) == 0) { sh[w] = s; sh[8 + w] = sq; }
    __syncthreads();
    float st = 0.f, sqt = 0.f;
#pragma unroll
    for (int i = 0; i < 8; i++) { st += sh[i]; sqt += sh[8 + i]; }
    const float mu   = st * (1.0f / D_DIM);
    const float var  = sqt * (1.0f / D_DIM) - mu * mu;
    const float rstd = rsqrtf(var + 1e-5f);
    float4 g4 = *(const float4*)(gamma + t * 4);
    float4 b4 = *(const float4*)(beta + t * 4);
    float4 o;
    o.x = (xv.x - mu) * rstd * g4.x + b4.x;
    o.y = (xv.y - mu) * rstd * g4.y + b4.y;
    o.z = (xv.z - mu) * rstd * g4.z + b4.z;
    o.w = (xv.w - mu) * rstd * g4.w + b4.w;
    *(float4*)(out + (size_t)row * D_DIM + t * 4) = o;
}

// ---------------------------------------------------------------------------
extern "C" void kernel_launch(void* const* d_in, const int* in_sizes, int n_in,
                              void* d_out, int out_size)
{
    const float* Q   = (const float*)d_in[0];
    const float* Kin = (const float*)d_in[1];
    const float* V   = (const float*)d_in[2];
    const int*   mask = (const int*)d_in[3];
    const float* Wq = (const float*)d_in[4];
    const float* bq = (const float*)d_in[5];
    const float* Wk = (const float*)d_in[6];
    const float* bk = (const float*)d_in[7];
    const float* Wv = (const float*)d_in[8];
    const float* bv = (const float*)d_in[9];
    const float* Wo = (const float*)d_in[10];
    const float* bo = (const float*)d_in[11];
    const float* gamma = (const float*)d_in[12];
    const float* beta  = (const float*)d_in[13];
    float* out = (float*)d_out;

    cudaFuncSetAttribute(attn_k, cudaFuncAttributeMaxDynamicSharedMemorySize, ATTN_SMEM_BYTES);

    dim3 gg(16, 32);  // (N/64, M/128)
    mm_k<0><<<gg, 256, GEMM_SMEM_BYTES>>>(Q,   Wq, bq, nullptr);
    mm_k<1><<<gg, 256, GEMM_SMEM_BYTES>>>(Kin, Wk, bk, nullptr);
    mm_k<2><<<gg, 256, GEMM_SMEM_BYTES>>>(V,   Wv, bv, nullptr);
    attn_k<<<dim3(16, 32), 256, ATTN_SMEM_BYTES>>>(mask);
    mm_k<3><<<gg, 256, GEMM_SMEM_BYTES>>>(nullptr, Wo, bo, Q);
    ln_k<<<4096, 256>>>(gamma, beta, out);
}

// round 6
// speedup vs baseline: 3.3937x; 2.0136x over previous
#include <cuda_runtime.h>
#include <cuda_bf16.h>
#include <mma.h>
#include <math.h>
#include <cstdint>

using namespace nvcuda;

#define S_LEN 2048
#define D_DIM 1024
#define NHEAD 16
#define HD 64
#define MROWS 4096

// Scratch (device globals: no allocations allowed)
__device__ __nv_bfloat16 g_q[MROWS * D_DIM];    // [b,h,s,d] bf16
__device__ __nv_bfloat16 g_k[MROWS * D_DIM];    // [b,h,s,d] bf16
__device__ __nv_bfloat16 g_v[MROWS * D_DIM];    // [b,h,s,d] bf16
__device__ __nv_bfloat16 g_ctx[MROWS * D_DIM];  // [b,s,h*64+d] bf16
__device__ float g_x[MROWS * D_DIM];            // pre-LN fp32

// ---------------------------------------------------------------------------
// helpers
// ---------------------------------------------------------------------------
__device__ __forceinline__ uint32_t smem_u32(const void* p) {
    return (uint32_t)__cvta_generic_to_shared(p);
}
__device__ __forceinline__ void cp16(uint32_t dst, const void* src) {
    asm volatile("cp.async.cg.shared.global [%0], [%1], 16;"
                 :: "r"(dst), "l"(src) : "memory");
}
#define CP_COMMIT() asm volatile("cp.async.commit_group;" ::: "memory")
#define CP_WAIT0()  asm volatile("cp.async.wait_group 0;" ::: "memory")

__device__ __forceinline__ void ldsm4(uint32_t& r0, uint32_t& r1,
                                      uint32_t& r2, uint32_t& r3, uint32_t a) {
    asm volatile("ldmatrix.sync.aligned.m8n8.x4.shared.b16 {%0,%1,%2,%3}, [%4];"
                 : "=r"(r0), "=r"(r1), "=r"(r2), "=r"(r3) : "r"(a));
}
__device__ __forceinline__ void ldsm4t(uint32_t& r0, uint32_t& r1,
                                       uint32_t& r2, uint32_t& r3, uint32_t a) {
    asm volatile("ldmatrix.sync.aligned.m8n8.x4.trans.shared.b16 {%0,%1,%2,%3}, [%4];"
                 : "=r"(r0), "=r"(r1), "=r"(r2), "=r"(r3) : "r"(a));
}
// D(16x8,f32) += A(16x16,bf16) * B(16x8,bf16)
__device__ __forceinline__ void mma16(float* d, uint32_t a0, uint32_t a1,
                                      uint32_t a2, uint32_t a3,
                                      uint32_t b0, uint32_t b1) {
    asm volatile(
        "mma.sync.aligned.m16n8k16.row.col.f32.bf16.bf16.f32 "
        "{%0,%1,%2,%3}, {%4,%5,%6,%7}, {%8,%9}, {%0,%1,%2,%3};"
        : "+f"(d[0]), "+f"(d[1]), "+f"(d[2]), "+f"(d[3])
        : "r"(a0), "r"(a1), "r"(a2), "r"(a3), "r"(b0), "r"(b1));
}
// pack two floats -> bf16x2 (lo in low 16 bits)
__device__ __forceinline__ uint32_t packbf(float lo, float hi) {
    uint32_t r;
    asm("cvt.rn.bf16x2.f32 %0, %1, %2;" : "=r"(r) : "f"(hi), "f"(lo));
    return r;
}

// ===========================================================================
// WMMA bf16 GEMM: C[4096x1024] = A @ W + bias. CTA tile 128x64, K-chunk 64.
// 8 warps of 32x32. MODE 0/1/2: bf16 head-layout scatter. MODE 3: +resid->g_x
// ===========================================================================
#define MM_SMEM_BYTES (128 * 72 * 4)   // float Cs alias is the largest

template <int MODE>
__global__ __launch_bounds__(256) void mm_k(
    const float* __restrict__ A,
    const float* __restrict__ W,
    const float* __restrict__ bias,
    const float* __restrict__ resid)
{
    extern __shared__ char smc[];
    __nv_bfloat16* As = (__nv_bfloat16*)smc;          // [128][72]
    __nv_bfloat16* Bs = As + 128 * 72;                // [64][72]
    float* Cs = (float*)smc;                          // [128][72] alias

    const int tid = threadIdx.x;
    const int wid = tid >> 5;
    const int wr = wid >> 1;
    const int wc = wid & 1;
    const int brow = blockIdx.y * 128;
    const int bcol = blockIdx.x * 64;

    wmma::fragment<wmma::accumulator, 16, 16, 16, float> acc[2][2];
#pragma unroll
    for (int mi = 0; mi < 2; mi++)
#pragma unroll
        for (int ni = 0; ni < 2; ni++)
            wmma::fill_fragment(acc[mi][ni], 0.0f);

    for (int kc = 0; kc < D_DIM; kc += 64) {
        // A tile 128x64
#pragma unroll
        for (int j = 0; j < 8; j++) {
            const int lin = tid + j * 256;
            const int r = lin >> 4;
            const int c4 = (lin & 15) << 2;
            if (MODE == 3) {
                *(uint2*)&As[r * 72 + c4] =
                    *(const uint2*)(g_ctx + (size_t)(brow + r) * D_DIM + kc + c4);
            } else {
                const float4 av = *(const float4*)(A + (size_t)(brow + r) * D_DIM + kc + c4);
                uint2 p;
                p.x = packbf(av.x, av.y);
                p.y = packbf(av.z, av.w);
                *(uint2*)&As[r * 72 + c4] = p;
            }
        }
        // W tile 64x64
#pragma unroll
        for (int j = 0; j < 4; j++) {
            const int lin = tid + j * 256;
            const int r = lin >> 4;
            const int c4 = (lin & 15) << 2;
            const float4 wv = *(const float4*)(W + (size_t)(kc + r) * D_DIM + bcol + c4);
            uint2 p;
            p.x = packbf(wv.x, wv.y);
            p.y = packbf(wv.z, wv.w);
            *(uint2*)&Bs[r * 72 + c4] = p;
        }
        __syncthreads();

#pragma unroll
        for (int k0 = 0; k0 < 64; k0 += 16) {
            wmma::fragment<wmma::matrix_a, 16, 16, 16, __nv_bfloat16,
                           wmma::row_major> af[2];
            wmma::fragment<wmma::matrix_b, 16, 16, 16, __nv_bfloat16,
                           wmma::row_major> bf[2];
#pragma unroll
            for (int mi = 0; mi < 2; mi++)
                wmma::load_matrix_sync(af[mi], &As[(wr * 32 + mi * 16) * 72 + k0], 72);
#pragma unroll
            for (int ni = 0; ni < 2; ni++)
                wmma::load_matrix_sync(bf[ni], &Bs[k0 * 72 + wc * 32 + ni * 16], 72);
#pragma unroll
            for (int mi = 0; mi < 2; mi++)
#pragma unroll
                for (int ni = 0; ni < 2; ni++)
                    wmma::mma_sync(acc[mi][ni], af[mi], bf[ni], acc[mi][ni]);
        }
        __syncthreads();
    }

#pragma unroll
    for (int mi = 0; mi < 2; mi++)
#pragma unroll
        for (int ni = 0; ni < 2; ni++)
            wmma::store_matrix_sync(&Cs[(wr * 32 + mi * 16) * 72 + wc * 32 + ni * 16],
                                    acc[mi][ni], 72, wmma::mem_row_major);
    __syncthreads();

#pragma unroll
    for (int j = 0; j < 8; j++) {
        const int lin = tid + j * 256;
        const int r = lin >> 4;
        const int c4 = (lin & 15) << 2;
        const int row = brow + r;
        const int col = bcol + c4;
        float4 cv = *(float4*)&Cs[r * 72 + c4];
        const float4 bi = *(const float4*)(bias + col);
        cv.x += bi.x; cv.y += bi.y; cv.z += bi.z; cv.w += bi.w;
        if (MODE == 3) {
            const float4 rv = *(const float4*)(resid + (size_t)row * D_DIM + col);
            cv.x += rv.x; cv.y += rv.y; cv.z += rv.z; cv.w += rv.w;
            *(float4*)(g_x + (size_t)row * D_DIM + col) = cv;
        } else {
            __nv_bfloat16* dst = (MODE == 0) ? g_q : (MODE == 1) ? g_k : g_v;
            const int bidx = row >> 11;
            const int sPos = row & 2047;
            const int hh = col >> 6;
            const int d = col & 63;
            uint2 p;
            p.x = packbf(cv.x, cv.y);
            p.y = packbf(cv.z, cv.w);
            *(uint2*)(dst + (((size_t)(bidx * NHEAD + hh) * S_LEN) + sPos) * HD + d) = p;
        }
    }
}

// ===========================================================================
// Flash attention: bf16 mma.m16n8k16 + ldmatrix, cp.async double-buffered KV.
// CTA = 128 q rows x one (b,h); 8 warps; warp = 16 q rows x 64-key tile.
// Mask is int32 (bool serialized as int32): nonzero = masked.
// ===========================================================================
// smem halfs: Q 128*72, K/V double-buffered 4*64*72
#define ATTN_SMEM_BYTES ((128 * 72 + 4 * 64 * 72) * 2)

__global__ __launch_bounds__(256) void attn_k(const int* __restrict__ mask)
{
    extern __shared__ __nv_bfloat16 smh[];
    __nv_bfloat16* qs = smh;                       // [128][72]
    const uint32_t qs_b = smem_u32(qs);
    const uint32_t kv_b0 = qs_b + 128 * 144;       // K buf0
    // layout: K0, V0, K1, V1 each 64*144 bytes
    uint32_t ks_b[2], vs_b[2];
    ks_b[0] = kv_b0;
    vs_b[0] = kv_b0 + 64 * 144;
    ks_b[1] = kv_b0 + 2 * 64 * 144;
    vs_b[1] = kv_b0 + 3 * 64 * 144;

    const int tid = threadIdx.x;
    const int lane = tid & 31;
    const int wid = tid >> 5;
    const int g = lane >> 2;
    const int t = lane & 3;

    const int bh = blockIdx.y;
    const int b = bh >> 4;
    const int h = bh & 15;
    const int q0 = blockIdx.x * 128;

    const __nv_bfloat16* qg = g_q + (size_t)bh * S_LEN * HD + (size_t)q0 * HD;
    const __nv_bfloat16* kg = g_k + (size_t)bh * S_LEN * HD;
    const __nv_bfloat16* vg = g_v + (size_t)bh * S_LEN * HD;

    // ---- prologue: async-load Q tile and KV tile 0 ----
#pragma unroll
    for (int j = 0; j < 4; j++) {
        const int lin = tid + j * 256;       // 1024 chunks of 16B
        const int r = lin >> 3;
        const int c8 = lin & 7;
        cp16(qs_b + r * 144 + c8 * 16, qg + r * 64 + c8 * 8);
    }
#pragma unroll
    for (int j = 0; j < 2; j++) {
        const int lin = tid + j * 256;       // 512 chunks
        const int r = lin >> 3;
        const int c8 = lin & 7;
        cp16(ks_b[0] + r * 144 + c8 * 16, kg + r * 64 + c8 * 8);
        cp16(vs_b[0] + r * 144 + c8 * 16, vg + r * 64 + c8 * 8);
    }
    CP_COMMIT();
    CP_WAIT0();
    __syncthreads();

    // ---- Q fragments pinned: 4 k-steps x 4 regs ----
    const int wrow = wid * 16;
    uint32_t qa[4][4];
#pragma unroll
    for (int s = 0; s < 4; s++) {
        const uint32_t a = qs_b + (wrow + (lane & 15)) * 144
                         + ((lane >> 4) * 8 + s * 16) * 2;
        ldsm4(qa[s][0], qa[s][1], qa[s][2], qa[s][3], a);
    }

    float o[8][4];
#pragma unroll
    for (int nt = 0; nt < 8; nt++)
#pragma unroll
        for (int e = 0; e < 4; e++) o[nt][e] = 0.f;
    float m0 = -INFINITY, m1 = -INFINITY, l0 = 0.f, l1 = 0.f;

    const int row0 = q0 + wrow + g;
    const int row1 = row0 + 8;
    const int* mrow0 = mask + (size_t)b * S_LEN * S_LEN + (size_t)row0 * S_LEN;
    const int* mrow1 = mask + (size_t)b * S_LEN * S_LEN + (size_t)row1 * S_LEN;

    for (int t0 = 0; t0 < 32; t0++) {
        // issue next KV tile into the other buffer
        if (t0 + 1 < 32) {
            const int nb = (t0 + 1) & 1;
            const size_t off = (size_t)(t0 + 1) * 64 * 64;
#pragma unroll
            for (int j = 0; j < 2; j++) {
                const int lin = tid + j * 256;
                const int r = lin >> 3;
                const int c8 = lin & 7;
                cp16(ks_b[nb] + r * 144 + c8 * 16, kg + off + r * 64 + c8 * 8);
                cp16(vs_b[nb] + r * 144 + c8 * 16, vg + off + r * 64 + c8 * 8);
            }
            CP_COMMIT();
        }

        const uint32_t kb = ks_b[t0 & 1];
        const uint32_t vb = vs_b[t0 & 1];
        const int k0g = t0 * 64;

        // ---- S = Q K^T ----
        float sacc[8][4];
#pragma unroll
        for (int nt = 0; nt < 8; nt++) {
            sacc[nt][0] = 0.f; sacc[nt][1] = 0.f;
            sacc[nt][2] = 0.f; sacc[nt][3] = 0.f;
            uint32_t kf[8];
            const uint32_t base = kb + (nt * 8 + (lane & 7)) * 144 + (lane >> 3) * 16;
            ldsm4(kf[0], kf[1], kf[2], kf[3], base);
            ldsm4(kf[4], kf[5], kf[6], kf[7], base + 64);
#pragma unroll
            for (int s = 0; s < 4; s++)
                mma16(sacc[nt], qa[s][0], qa[s][1], qa[s][2], qa[s][3],
                      kf[2 * s], kf[2 * s + 1]);
        }

        // ---- scale + mask ----
#pragma unroll
        for (int nt = 0; nt < 8; nt++) {
            const int cpos = k0g + nt * 8 + 2 * t;
            const int2 mv0 = *(const int2*)(mrow0 + cpos);
            const int2 mv1 = *(const int2*)(mrow1 + cpos);
            sacc[nt][0] = mv0.x ? -1e9f : sacc[nt][0] * 0.125f;
            sacc[nt][1] = mv0.y ? -1e9f : sacc[nt][1] * 0.125f;
            sacc[nt][2] = mv1.x ? -1e9f : sacc[nt][2] * 0.125f;
            sacc[nt][3] = mv1.y ? -1e9f : sacc[nt][3] * 0.125f;
        }

        // ---- online softmax ----
        float mx0 = -INFINITY, mx1 = -INFINITY;
#pragma unroll
        for (int nt = 0; nt < 8; nt++) {
            mx0 = fmaxf(mx0, fmaxf(sacc[nt][0], sacc[nt][1]));
            mx1 = fmaxf(mx1, fmaxf(sacc[nt][2], sacc[nt][3]));
        }
        mx0 = fmaxf(mx0, __shfl_xor_sync(0xffffffffu, mx0, 1));
        mx0 = fmaxf(mx0, __shfl_xor_sync(0xffffffffu, mx0, 2));
        mx1 = fmaxf(mx1, __shfl_xor_sync(0xffffffffu, mx1, 1));
        mx1 = fmaxf(mx1, __shfl_xor_sync(0xffffffffu, mx1, 2));
        const float mn0 = fmaxf(m0, mx0);
        const float mn1 = fmaxf(m1, mx1);
        const float cr0 = __expf(m0 - mn0);
        const float cr1 = __expf(m1 - mn1);
        float sum0 = 0.f, sum1 = 0.f;
#pragma unroll
        for (int nt = 0; nt < 8; nt++) {
            sacc[nt][0] = __expf(sacc[nt][0] - mn0);
            sacc[nt][1] = __expf(sacc[nt][1] - mn0);
            sacc[nt][2] = __expf(sacc[nt][2] - mn1);
            sacc[nt][3] = __expf(sacc[nt][3] - mn1);
            sum0 += sacc[nt][0] + sacc[nt][1];
            sum1 += sacc[nt][2] + sacc[nt][3];
        }
        sum0 += __shfl_xor_sync(0xffffffffu, sum0, 1);
        sum0 += __shfl_xor_sync(0xffffffffu, sum0, 2);
        sum1 += __shfl_xor_sync(0xffffffffu, sum1, 1);
        sum1 += __shfl_xor_sync(0xffffffffu, sum1, 2);
        l0 = l0 * cr0 + sum0;
        l1 = l1 * cr1 + sum1;
        m0 = mn0; m1 = mn1;
#pragma unroll
        for (int nt = 0; nt < 8; nt++) {
            o[nt][0] *= cr0; o[nt][1] *= cr0;
            o[nt][2] *= cr1; o[nt][3] *= cr1;
        }

        // ---- O += P V (P packs straight into A fragments) ----
#pragma unroll
        for (int s = 0; s < 4; s++) {
            const uint32_t a0 = packbf(sacc[2 * s][0], sacc[2 * s][1]);
            const uint32_t a1 = packbf(sacc[2 * s][2], sacc[2 * s][3]);
            const uint32_t a2 = packbf(sacc[2 * s + 1][0], sacc[2 * s + 1][1]);
            const uint32_t a3 = packbf(sacc[2 * s + 1][2], sacc[2 * s + 1][3]);
            const uint32_t vrow = s * 16 + ((lane >> 3) & 1) * 8 + (lane & 7);
#pragma unroll
            for (int np = 0; np < 4; np++) {
                uint32_t v0, v1, v2, v3;
                ldsm4t(v0, v1, v2, v3,
                       vb + vrow * 144 + (np * 2 + (lane >> 4)) * 16);
                mma16(o[np * 2],     a0, a1, a2, a3, v0, v1);
                mma16(o[np * 2 + 1], a0, a1, a2, a3, v2, v3);
            }
        }

        if (t0 + 1 < 32) {
            CP_WAIT0();
            __syncthreads();
        }
    }

    // ---- epilogue: ctx[b][s][h*64+d] = O / l (bf16) ----
    const float inv0 = 1.0f / l0;
    const float inv1 = 1.0f / l1;
#pragma unroll
    for (int nt = 0; nt < 8; nt++) {
        const int col = h * 64 + nt * 8 + 2 * t;
        *(uint32_t*)(g_ctx + (size_t)(b * S_LEN + row0) * D_DIM + col) =
            packbf(o[nt][0] * inv0, o[nt][1] * inv0);
        *(uint32_t*)(g_ctx + (size_t)(b * S_LEN + row1) * D_DIM + col) =
            packbf(o[nt][2] * inv1, o[nt][3] * inv1);
    }
}

// ---------------------------------------------------------------------------
// LayerNorm over last dim (1024), one block per row.
// ---------------------------------------------------------------------------
__global__ __launch_bounds__(256) void ln_k(const float* __restrict__ gamma,
                                            const float* __restrict__ beta,
                                            float* __restrict__ out)
{
    const int row = blockIdx.x;
    const int t = threadIdx.x;
    const float* x = g_x + (size_t)row * D_DIM;
    float4 xv = *(const float4*)(x + t * 4);
    float s  = (xv.x + xv.y) + (xv.z + xv.w);
    float sq = xv.x * xv.x + xv.y * xv.y + xv.z * xv.z + xv.w * xv.w;
#pragma unroll
    for (int off = 16; off; off >>= 1) {
        s  += __shfl_xor_sync(0xffffffffu, s, off);
        sq += __shfl_xor_sync(0xffffffffu, sq, off);
    }
    __shared__ float sh[16];
    const int w = t >> 5;
    if ((t & 31) == 0) { sh[w] = s; sh[8 + w] = sq; }
    __syncthreads();
    float st = 0.f, sqt = 0.f;
#pragma unroll
    for (int i = 0; i < 8; i++) { st += sh[i]; sqt += sh[8 + i]; }
    const float mu   = st * (1.0f / D_DIM);
    const float var  = sqt * (1.0f / D_DIM) - mu * mu;
    const float rstd = rsqrtf(var + 1e-5f);
    float4 g4 = *(const float4*)(gamma + t * 4);
    float4 b4 = *(const float4*)(beta + t * 4);
    float4 o;
    o.x = (xv.x - mu) * rstd * g4.x + b4.x;
    o.y = (xv.y - mu) * rstd * g4.y + b4.y;
    o.z = (xv.z - mu) * rstd * g4.z + b4.z;
    o.w = (xv.w - mu) * rstd * g4.w + b4.w;
    *(float4*)(out + (size_t)row * D_DIM + t * 4) = o;
}

// ---------------------------------------------------------------------------
extern "C" void kernel_launch(void* const* d_in, const int* in_sizes, int n_in,
                              void* d_out, int out_size)
{
    const float* Q   = (const float*)d_in[0];
    const float* Kin = (const float*)d_in[1];
    const float* V   = (const float*)d_in[2];
    const int*   mask = (const int*)d_in[3];
    const float* Wq = (const float*)d_in[4];
    const float* bq = (const float*)d_in[5];
    const float* Wk = (const float*)d_in[6];
    const float* bk = (const float*)d_in[7];
    const float* Wv = (const float*)d_in[8];
    const float* bv = (const float*)d_in[9];
    const float* Wo = (const float*)d_in[10];
    const float* bo = (const float*)d_in[11];
    const float* gamma = (const float*)d_in[12];
    const float* beta  = (const float*)d_in[13];
    float* out = (float*)d_out;

    cudaFuncSetAttribute(attn_k, cudaFuncAttributeMaxDynamicSharedMemorySize, ATTN_SMEM_BYTES);
    cudaFuncSetAttribute(mm_k<0>, cudaFuncAttributeMaxDynamicSharedMemorySize, MM_SMEM_BYTES);
    cudaFuncSetAttribute(mm_k<1>, cudaFuncAttributeMaxDynamicSharedMemorySize, MM_SMEM_BYTES);
    cudaFuncSetAttribute(mm_k<2>, cudaFuncAttributeMaxDynamicSharedMemorySize, MM_SMEM_BYTES);
    cudaFuncSetAttribute(mm_k<3>, cudaFuncAttributeMaxDynamicSharedMemorySize, MM_SMEM_BYTES);

    dim3 gg(16, 32);  // (N/64, M/128)
    mm_k<0><<<gg, 256, MM_SMEM_BYTES>>>(Q,   Wq, bq, nullptr);
    mm_k<1><<<gg, 256, MM_SMEM_BYTES>>>(Kin, Wk, bk, nullptr);
    mm_k<2><<<gg, 256, MM_SMEM_BYTES>>>(V,   Wv, bv, nullptr);
    attn_k<<<dim3(16, 32), 256, ATTN_SMEM_BYTES>>>(mask);
    mm_k<3><<<gg, 256, MM_SMEM_BYTES>>>(nullptr, Wo, bo, Q);
    ln_k<<<4096, 256>>>(gamma, beta, out);
}

// round 7
// speedup vs baseline: 4.6709x; 1.3763x over previous
#include <cuda_runtime.h>
#include <cuda_bf16.h>
#include <mma.h>
#include <math.h>
#include <cstdint>

using namespace nvcuda;

#define S_LEN 2048
#define D_DIM 1024
#define NHEAD 16
#define HD 64
#define MROWS 4096

// Scratch (device globals: no allocations allowed)
__device__ __nv_bfloat16 g_q[MROWS * D_DIM];    // [b,h,s,d] bf16
__device__ __nv_bfloat16 g_k[MROWS * D_DIM];    // [b,h,s,d] bf16
__device__ __nv_bfloat16 g_v[MROWS * D_DIM];    // [b,h,s,d] bf16
__device__ __nv_bfloat16 g_ctx[MROWS * D_DIM];  // [b,s,h*64+d] bf16
__device__ float g_x[MROWS * D_DIM];            // pre-LN fp32
__device__ uint32_t g_mbits[2 * S_LEN * (S_LEN / 32)];  // packed mask bits

// ---------------------------------------------------------------------------
// helpers
// ---------------------------------------------------------------------------
__device__ __forceinline__ uint32_t smem_u32(const void* p) {
    return (uint32_t)__cvta_generic_to_shared(p);
}
__device__ __forceinline__ void cp16(uint32_t dst, const void* src) {
    asm volatile("cp.async.cg.shared.global [%0], [%1], 16;"
                 :: "r"(dst), "l"(src) : "memory");
}
#define CP_COMMIT() asm volatile("cp.async.commit_group;" ::: "memory")
#define CP_WAIT0()  asm volatile("cp.async.wait_group 0;" ::: "memory")

__device__ __forceinline__ void ldsm4(uint32_t& r0, uint32_t& r1,
                                      uint32_t& r2, uint32_t& r3, uint32_t a) {
    asm volatile("ldmatrix.sync.aligned.m8n8.x4.shared.b16 {%0,%1,%2,%3}, [%4];"
                 : "=r"(r0), "=r"(r1), "=r"(r2), "=r"(r3) : "r"(a));
}
__device__ __forceinline__ void ldsm4t(uint32_t& r0, uint32_t& r1,
                                       uint32_t& r2, uint32_t& r3, uint32_t a) {
    asm volatile("ldmatrix.sync.aligned.m8n8.x4.trans.shared.b16 {%0,%1,%2,%3}, [%4];"
                 : "=r"(r0), "=r"(r1), "=r"(r2), "=r"(r3) : "r"(a));
}
// D(16x8,f32) += A(16x16,bf16) * B(16x8,bf16)
__device__ __forceinline__ void mma16(float* d, uint32_t a0, uint32_t a1,
                                      uint32_t a2, uint32_t a3,
                                      uint32_t b0, uint32_t b1) {
    asm volatile(
        "mma.sync.aligned.m16n8k16.row.col.f32.bf16.bf16.f32 "
        "{%0,%1,%2,%3}, {%4,%5,%6,%7}, {%8,%9}, {%0,%1,%2,%3};"
        : "+f"(d[0]), "+f"(d[1]), "+f"(d[2]), "+f"(d[3])
        : "r"(a0), "r"(a1), "r"(a2), "r"(a3), "r"(b0), "r"(b1));
}
// pack two floats -> bf16x2 (lo in low 16 bits)
__device__ __forceinline__ uint32_t packbf(float lo, float hi) {
    uint32_t r;
    asm("cvt.rn.bf16x2.f32 %0, %1, %2;" : "=r"(r) : "f"(hi), "f"(lo));
    return r;
}

// ===========================================================================
// Mask bit-pack: g_mbits[b*2048+row][word] = ballot of mask[row][word*32+lane]
// ===========================================================================
__global__ __launch_bounds__(256) void mb_k(const int* __restrict__ mask)
{
    const int rr = blockIdx.x;              // 0..4095 (b*2048 + row)
    const int w = threadIdx.x >> 5;         // warp 0..7
    const int lane = threadIdx.x & 31;
    const int* mrow = mask + (size_t)rr * S_LEN;
    uint32_t* obase = g_mbits + (size_t)rr * (S_LEN / 32);
#pragma unroll
    for (int i = 0; i < 8; i++) {
        const int word = w + i * 8;
        const uint32_t bal =
            __ballot_sync(0xffffffffu, mrow[word * 32 + lane] != 0);
        if (lane == 0) obase[word] = bal;
    }
}

// ===========================================================================
// WMMA bf16 GEMM: C[4096x1024] = A @ W + bias. CTA tile 128x128, K-chunk 64.
// 8 warps of 32x64. MODE 0/1/2: bf16 head-layout scatter. MODE 3: +resid->g_x
// ===========================================================================
#define MM_SMEM_BYTES (128 * 136 * 4)   // float Cs alias is the largest

template <int MODE>
__global__ __launch_bounds__(256) void mm_k(
    const float* __restrict__ A,
    const float* __restrict__ W,
    const float* __restrict__ bias,
    const float* __restrict__ resid)
{
    extern __shared__ char smc[];
    __nv_bfloat16* As = (__nv_bfloat16*)smc;          // [128][72]
    __nv_bfloat16* Bs = As + 128 * 72;                // [64][136]
    float* Cs = (float*)smc;                          // [128][136] alias

    const int tid = threadIdx.x;
    const int wid = tid >> 5;
    const int wm0 = (wid & 3) * 32;
    const int wn0 = (wid >> 2) * 64;
    const int brow = blockIdx.y * 128;
    const int bcol = blockIdx.x * 128;

    wmma::fragment<wmma::accumulator, 16, 16, 16, float> acc[2][4];
#pragma unroll
    for (int mi = 0; mi < 2; mi++)
#pragma unroll
        for (int ni = 0; ni < 4; ni++)
            wmma::fill_fragment(acc[mi][ni], 0.0f);

    for (int kc = 0; kc < D_DIM; kc += 64) {
        // A tile 128x64
#pragma unroll
        for (int j = 0; j < 8; j++) {
            const int lin = tid + j * 256;      // 2048 float4-equivalents
            const int r = lin >> 4;
            const int c4 = (lin & 15) << 2;
            if (MODE == 3) {
                *(uint2*)&As[r * 72 + c4] =
                    *(const uint2*)(g_ctx + (size_t)(brow + r) * D_DIM + kc + c4);
            } else {
                const float4 av = *(const float4*)(A + (size_t)(brow + r) * D_DIM + kc + c4);
                uint2 p;
                p.x = packbf(av.x, av.y);
                p.y = packbf(av.z, av.w);
                *(uint2*)&As[r * 72 + c4] = p;
            }
        }
        // W tile 64x128
#pragma unroll
        for (int j = 0; j < 8; j++) {
            const int lin = tid + j * 256;      // 2048 float4s
            const int r = lin >> 5;
            const int c4 = (lin & 31) << 2;
            const float4 wv = *(const float4*)(W + (size_t)(kc + r) * D_DIM + bcol + c4);
            uint2 p;
            p.x = packbf(wv.x, wv.y);
            p.y = packbf(wv.z, wv.w);
            *(uint2*)&Bs[r * 136 + c4] = p;
        }
        __syncthreads();

#pragma unroll
        for (int k0 = 0; k0 < 64; k0 += 16) {
            wmma::fragment<wmma::matrix_a, 16, 16, 16, __nv_bfloat16,
                           wmma::row_major> af[2];
            wmma::fragment<wmma::matrix_b, 16, 16, 16, __nv_bfloat16,
                           wmma::row_major> bf[4];
#pragma unroll
            for (int mi = 0; mi < 2; mi++)
                wmma::load_matrix_sync(af[mi], &As[(wm0 + mi * 16) * 72 + k0], 72);
#pragma unroll
            for (int ni = 0; ni < 4; ni++)
                wmma::load_matrix_sync(bf[ni], &Bs[k0 * 136 + wn0 + ni * 16], 136);
#pragma unroll
            for (int mi = 0; mi < 2; mi++)
#pragma unroll
                for (int ni = 0; ni < 4; ni++)
                    wmma::mma_sync(acc[mi][ni], af[mi], bf[ni], acc[mi][ni]);
        }
        __syncthreads();
    }

#pragma unroll
    for (int mi = 0; mi < 2; mi++)
#pragma unroll
        for (int ni = 0; ni < 4; ni++)
            wmma::store_matrix_sync(&Cs[(wm0 + mi * 16) * 136 + wn0 + ni * 16],
                                    acc[mi][ni], 136, wmma::mem_row_major);
    __syncthreads();

#pragma unroll
    for (int j = 0; j < 16; j++) {
        const int lin = tid + j * 256;          // 4096 float4s
        const int r = lin >> 5;
        const int c4 = (lin & 31) << 2;
        const int row = brow + r;
        const int col = bcol + c4;
        float4 cv = *(float4*)&Cs[r * 136 + c4];
        const float4 bi = *(const float4*)(bias + col);
        cv.x += bi.x; cv.y += bi.y; cv.z += bi.z; cv.w += bi.w;
        if (MODE == 3) {
            const float4 rv = *(const float4*)(resid + (size_t)row * D_DIM + col);
            cv.x += rv.x; cv.y += rv.y; cv.z += rv.z; cv.w += rv.w;
            *(float4*)(g_x + (size_t)row * D_DIM + col) = cv;
        } else {
            __nv_bfloat16* dst = (MODE == 0) ? g_q : (MODE == 1) ? g_k : g_v;
            const int bidx = row >> 11;
            const int sPos = row & 2047;
            const int hh = col >> 6;
            const int d = col & 63;
            uint2 p;
            p.x = packbf(cv.x, cv.y);
            p.y = packbf(cv.z, cv.w);
            *(uint2*)(dst + (((size_t)(bidx * NHEAD + hh) * S_LEN) + sPos) * HD + d) = p;
        }
    }
}

// ===========================================================================
// Flash attention: bf16 mma.m16n8k16 + ldmatrix, cp.async double-buffered KV.
// CTA = 128 q rows x one (b,h); 8 warps; warp = 16 q rows x 64-key tile.
// Q smem region is reused as KV stage-1 buffer after Q fragments are pinned.
// Mask comes from the packed bitfield g_mbits (2 x uint2 loads per tile).
// ===========================================================================
// smem: region X (Q, later K1V1) 18432 B + region Y (K0V0) 18432 B
#define ATTN_SMEM_BYTES (2 * 18432)

__global__ __launch_bounds__(256, 2) void attn_k()
{
    extern __shared__ __nv_bfloat16 smh[];
    const uint32_t base = smem_u32(smh);
    const uint32_t qs_b = base;                    // Q region (X)
    uint32_t ks_b[2], vs_b[2];
    ks_b[0] = base + 18432;                        // Y
    vs_b[0] = base + 18432 + 9216;
    ks_b[1] = base;                                // X (overlaps Q)
    vs_b[1] = base + 9216;

    const int tid = threadIdx.x;
    const int lane = tid & 31;
    const int wid = tid >> 5;
    const int g = lane >> 2;
    const int t = lane & 3;

    const int bh = blockIdx.y;
    const int b = bh >> 4;
    const int h = bh & 15;
    const int q0 = blockIdx.x * 128;

    const __nv_bfloat16* qg = g_q + (size_t)bh * S_LEN * HD + (size_t)q0 * HD;
    const __nv_bfloat16* kg = g_k + (size_t)bh * S_LEN * HD;
    const __nv_bfloat16* vg = g_v + (size_t)bh * S_LEN * HD;

    // ---- prologue: async-load Q tile and KV tile 0 ----
#pragma unroll
    for (int j = 0; j < 4; j++) {
        const int lin = tid + j * 256;       // 1024 chunks of 16B
        const int r = lin >> 3;
        const int c8 = lin & 7;
        cp16(qs_b + r * 144 + c8 * 16, qg + r * 64 + c8 * 8);
    }
#pragma unroll
    for (int j = 0; j < 2; j++) {
        const int lin = tid + j * 256;       // 512 chunks
        const int r = lin >> 3;
        const int c8 = lin & 7;
        cp16(ks_b[0] + r * 144 + c8 * 16, kg + r * 64 + c8 * 8);
        cp16(vs_b[0] + r * 144 + c8 * 16, vg + r * 64 + c8 * 8);
    }
    CP_COMMIT();
    CP_WAIT0();
    __syncthreads();

    // ---- Q fragments pinned: 4 k-steps x 4 regs ----
    const int wrow = wid * 16;
    uint32_t qa[4][4];
#pragma unroll
    for (int s = 0; s < 4; s++) {
        const uint32_t a = qs_b + (wrow + (lane & 15)) * 144
                         + ((lane >> 4) * 8 + s * 16) * 2;
        ldsm4(qa[s][0], qa[s][1], qa[s][2], qa[s][3], a);
    }
    __syncthreads();   // all warps done reading Q before X is overwritten

    float o[8][4];
#pragma unroll
    for (int nt = 0; nt < 8; nt++)
#pragma unroll
        for (int e = 0; e < 4; e++) o[nt][e] = 0.f;
    float m0 = -INFINITY, m1 = -INFINITY, l0 = 0.f, l1 = 0.f;

    const int row0 = q0 + wrow + g;
    const int row1 = row0 + 8;
    const uint32_t* mb0 = g_mbits + (size_t)(b * S_LEN + row0) * (S_LEN / 32);
    const uint32_t* mb1 = g_mbits + (size_t)(b * S_LEN + row1) * (S_LEN / 32);

    for (int t0 = 0; t0 < 32; t0++) {
        // issue next KV tile into the other buffer
        if (t0 + 1 < 32) {
            const int nb = (t0 + 1) & 1;
            const size_t off = (size_t)(t0 + 1) * 64 * 64;
#pragma unroll
            for (int j = 0; j < 2; j++) {
                const int lin = tid + j * 256;
                const int r = lin >> 3;
                const int c8 = lin & 7;
                cp16(ks_b[nb] + r * 144 + c8 * 16, kg + off + r * 64 + c8 * 8);
                cp16(vs_b[nb] + r * 144 + c8 * 16, vg + off + r * 64 + c8 * 8);
            }
            CP_COMMIT();
        }

        const uint32_t kb = ks_b[t0 & 1];
        const uint32_t vb = vs_b[t0 & 1];

        // ---- S = Q K^T ----
        float sacc[8][4];
#pragma unroll
        for (int nt = 0; nt < 8; nt++) {
            sacc[nt][0] = 0.f; sacc[nt][1] = 0.f;
            sacc[nt][2] = 0.f; sacc[nt][3] = 0.f;
            uint32_t kf[8];
            const uint32_t kaddr = kb + (nt * 8 + (lane & 7)) * 144 + (lane >> 3) * 16;
            ldsm4(kf[0], kf[1], kf[2], kf[3], kaddr);
            ldsm4(kf[4], kf[5], kf[6], kf[7], kaddr + 64);
#pragma unroll
            for (int s = 0; s < 4; s++)
                mma16(sacc[nt], qa[s][0], qa[s][1], qa[s][2], qa[s][3],
                      kf[2 * s], kf[2 * s + 1]);
        }

        // ---- scale + mask (packed bits: one uint2 per row per tile) ----
        const uint2 mw0 = *(const uint2*)(mb0 + t0 * 2);
        const uint2 mw1 = *(const uint2*)(mb1 + t0 * 2);
#pragma unroll
        for (int nt = 0; nt < 8; nt++) {
            const int sh = (nt * 8 + 2 * t) & 31;
            const uint32_t w0 = ((nt < 4) ? mw0.x : mw0.y) >> sh;
            const uint32_t w1 = ((nt < 4) ? mw1.x : mw1.y) >> sh;
            sacc[nt][0] = (w0 & 1u) ? -1e9f : sacc[nt][0] * 0.125f;
            sacc[nt][1] = (w0 & 2u) ? -1e9f : sacc[nt][1] * 0.125f;
            sacc[nt][2] = (w1 & 1u) ? -1e9f : sacc[nt][2] * 0.125f;
            sacc[nt][3] = (w1 & 2u) ? -1e9f : sacc[nt][3] * 0.125f;
        }

        // ---- online softmax ----
        float mx0 = -INFINITY, mx1 = -INFINITY;
#pragma unroll
        for (int nt = 0; nt < 8; nt++) {
            mx0 = fmaxf(mx0, fmaxf(sacc[nt][0], sacc[nt][1]));
            mx1 = fmaxf(mx1, fmaxf(sacc[nt][2], sacc[nt][3]));
        }
        mx0 = fmaxf(mx0, __shfl_xor_sync(0xffffffffu, mx0, 1));
        mx0 = fmaxf(mx0, __shfl_xor_sync(0xffffffffu, mx0, 2));
        mx1 = fmaxf(mx1, __shfl_xor_sync(0xffffffffu, mx1, 1));
        mx1 = fmaxf(mx1, __shfl_xor_sync(0xffffffffu, mx1, 2));
        const float mn0 = fmaxf(m0, mx0);
        const float mn1 = fmaxf(m1, mx1);
        const float cr0 = __expf(m0 - mn0);
        const float cr1 = __expf(m1 - mn1);
        float sum0 = 0.f, sum1 = 0.f;
#pragma unroll
        for (int nt = 0; nt < 8; nt++) {
            sacc[nt][0] = __expf(sacc[nt][0] - mn0);
            sacc[nt][1] = __expf(sacc[nt][1] - mn0);
            sacc[nt][2] = __expf(sacc[nt][2] - mn1);
            sacc[nt][3] = __expf(sacc[nt][3] - mn1);
            sum0 += sacc[nt][0] + sacc[nt][1];
            sum1 += sacc[nt][2] + sacc[nt][3];
        }
        sum0 += __shfl_xor_sync(0xffffffffu, sum0, 1);
        sum0 += __shfl_xor_sync(0xffffffffu, sum0, 2);
        sum1 += __shfl_xor_sync(0xffffffffu, sum1, 1);
        sum1 += __shfl_xor_sync(0xffffffffu, sum1, 2);
        l0 = l0 * cr0 + sum0;
        l1 = l1 * cr1 + sum1;
        m0 = mn0; m1 = mn1;
#pragma unroll
        for (int nt = 0; nt < 8; nt++) {
            o[nt][0] *= cr0; o[nt][1] *= cr0;
            o[nt][2] *= cr1; o[nt][3] *= cr1;
        }

        // ---- O += P V (P packs straight into A fragments) ----
#pragma unroll
        for (int s = 0; s < 4; s++) {
            const uint32_t a0 = packbf(sacc[2 * s][0], sacc[2 * s][1]);
            const uint32_t a1 = packbf(sacc[2 * s][2], sacc[2 * s][3]);
            const uint32_t a2 = packbf(sacc[2 * s + 1][0], sacc[2 * s + 1][1]);
            const uint32_t a3 = packbf(sacc[2 * s + 1][2], sacc[2 * s + 1][3]);
            const uint32_t vrow = s * 16 + ((lane >> 3) & 1) * 8 + (lane & 7);
#pragma unroll
            for (int np = 0; np < 4; np++) {
                uint32_t v0, v1, v2, v3;
                ldsm4t(v0, v1, v2, v3,
                       vb + vrow * 144 + (np * 2 + (lane >> 4)) * 16);
                mma16(o[np * 2],     a0, a1, a2, a3, v0, v1);
                mma16(o[np * 2 + 1], a0, a1, a2, a3, v2, v3);
            }
        }

        if (t0 + 1 < 32) {
            CP_WAIT0();
            __syncthreads();
        }
    }

    // ---- epilogue: ctx[b][s][h*64+d] = O / l (bf16) ----
    const float inv0 = 1.0f / l0;
    const float inv1 = 1.0f / l1;
#pragma unroll
    for (int nt = 0; nt < 8; nt++) {
        const int col = h * 64 + nt * 8 + 2 * t;
        *(uint32_t*)(g_ctx + (size_t)(b * S_LEN + row0) * D_DIM + col) =
            packbf(o[nt][0] * inv0, o[nt][1] * inv0);
        *(uint32_t*)(g_ctx + (size_t)(b * S_LEN + row1) * D_DIM + col) =
            packbf(o[nt][2] * inv1, o[nt][3] * inv1);
    }
}

// ---------------------------------------------------------------------------
// LayerNorm over last dim (1024), one block per row.
// ---------------------------------------------------------------------------
__global__ __launch_bounds__(256) void ln_k(const float* __restrict__ gamma,
                                            const float* __restrict__ beta,
                                            float* __restrict__ out)
{
    const int row = blockIdx.x;
    const int t = threadIdx.x;
    const float* x = g_x + (size_t)row * D_DIM;
    float4 xv = *(const float4*)(x + t * 4);
    float s  = (xv.x + xv.y) + (xv.z + xv.w);
    float sq = xv.x * xv.x + xv.y * xv.y + xv.z * xv.z + xv.w * xv.w;
#pragma unroll
    for (int off = 16; off; off >>= 1) {
        s  += __shfl_xor_sync(0xffffffffu, s, off);
        sq += __shfl_xor_sync(0xffffffffu, sq, off);
    }
    __shared__ float sh[16];
    const int w = t >> 5;
    if ((t & 31) == 0) { sh[w] = s; sh[8 + w] = sq; }
    __syncthreads();
    float st = 0.f, sqt = 0.f;
#pragma unroll
    for (int i = 0; i < 8; i++) { st += sh[i]; sqt += sh[8 + i]; }
    const float mu   = st * (1.0f / D_DIM);
    const float var  = sqt * (1.0f / D_DIM) - mu * mu;
    const float rstd = rsqrtf(var + 1e-5f);
    float4 g4 = *(const float4*)(gamma + t * 4);
    float4 b4 = *(const float4*)(beta + t * 4);
    float4 o;
    o.x = (xv.x - mu) * rstd * g4.x + b4.x;
    o.y = (xv.y - mu) * rstd * g4.y + b4.y;
    o.z = (xv.z - mu) * rstd * g4.z + b4.z;
    o.w = (xv.w - mu) * rstd * g4.w + b4.w;
    *(float4*)(out + (size_t)row * D_DIM + t * 4) = o;
}

// ---------------------------------------------------------------------------
extern "C" void kernel_launch(void* const* d_in, const int* in_sizes, int n_in,
                              void* d_out, int out_size)
{
    const float* Q   = (const float*)d_in[0];
    const float* Kin = (const float*)d_in[1];
    const float* V   = (const float*)d_in[2];
    const int*   mask = (const int*)d_in[3];
    const float* Wq = (const float*)d_in[4];
    const float* bq = (const float*)d_in[5];
    const float* Wk = (const float*)d_in[6];
    const float* bk = (const float*)d_in[7];
    const float* Wv = (const float*)d_in[8];
    const float* bv = (const float*)d_in[9];
    const float* Wo = (const float*)d_in[10];
    const float* bo = (const float*)d_in[11];
    const float* gamma = (const float*)d_in[12];
    const float* beta  = (const float*)d_in[13];
    float* out = (float*)d_out;

    cudaFuncSetAttribute(attn_k, cudaFuncAttributeMaxDynamicSharedMemorySize, ATTN_SMEM_BYTES);
    cudaFuncSetAttribute(mm_k<0>, cudaFuncAttributeMaxDynamicSharedMemorySize, MM_SMEM_BYTES);
    cudaFuncSetAttribute(mm_k<1>, cudaFuncAttributeMaxDynamicSharedMemorySize, MM_SMEM_BYTES);
    cudaFuncSetAttribute(mm_k<2>, cudaFuncAttributeMaxDynamicSharedMemorySize, MM_SMEM_BYTES);
    cudaFuncSetAttribute(mm_k<3>, cudaFuncAttributeMaxDynamicSharedMemorySize, MM_SMEM_BYTES);

    mb_k<<<2 * S_LEN, 256>>>(mask);

    dim3 gg(8, 32);  // (N/128, M/128)
    mm_k<0><<<gg, 256, MM_SMEM_BYTES>>>(Q,   Wq, bq, nullptr);
    mm_k<1><<<gg, 256, MM_SMEM_BYTES>>>(Kin, Wk, bk, nullptr);
    mm_k<2><<<gg, 256, MM_SMEM_BYTES>>>(V,   Wv, bv, nullptr);
    attn_k<<<dim3(16, 32), 256, ATTN_SMEM_BYTES>>>();
    mm_k<3><<<gg, 256, MM_SMEM_BYTES>>>(nullptr, Wo, bo, Q);
    ln_k<<<4096, 256>>>(gamma, beta, out);
}